// round 3
// baseline (speedup 1.0000x reference)
#include <cuda_runtime.h>
#include <cuda_bf16.h>
#include <math.h>

// Problem constants
#define BB 2
#define SS 2048
#define HID 2048
#define HQ 32
#define HKV 4
#define DH 128
#define ROWS (BB*SS)          // 4096
#define QCOLS (HQ*DH)         // 4096
#define KVCOLS (HKV*DH)       // 512
#define SCALE 0.08838834764831845f
#define EPS 1e-6f

// Scratch (device globals; zero-init BSS, no allocation)
__device__ float g_q[(size_t)ROWS * QCOLS];
__device__ float g_k[(size_t)ROWS * KVCOLS];
__device__ float g_v[(size_t)ROWS * KVCOLS];
__device__ float g_o[(size_t)ROWS * QCOLS];

// ---------------------------------------------------------------------------
// SGEMM: C[M,N] = A[M,K] @ B[K,N], all row-major fp32.
// 128x128 block, BK=8, 256 threads, 8x8 per thread.
// M%128==0, N%128==0, K%8==0 guaranteed by caller.
// ---------------------------------------------------------------------------
__global__ __launch_bounds__(256) void sgemm_kernel(
    const float* __restrict__ A, const float* __restrict__ B,
    float* __restrict__ C, int M, int N, int K)
{
    __shared__ float As[8][128];
    __shared__ float Bs[8][128];

    const int bm = blockIdx.y * 128;
    const int bn = blockIdx.x * 128;
    const int t  = threadIdx.x;
    const int ty = t >> 4;          // 0..15
    const int tx = t & 15;          // 0..15

    // global load mapping
    const int arow = t >> 1;        // 0..127
    const int acol = (t & 1) * 4;   // 0 or 4
    const int brow = t >> 5;        // 0..7
    const int bcol = (t & 31) * 4;  // 0..124

    const float* Aptr = A + (size_t)(bm + arow) * K + acol;
    const float* Bptr = B + (size_t)brow * N + bn + bcol;

    float acc[8][8];
#pragma unroll
    for (int i = 0; i < 8; i++)
#pragma unroll
        for (int j = 0; j < 8; j++) acc[i][j] = 0.f;

    for (int k0 = 0; k0 < K; k0 += 8) {
        float4 av = *(const float4*)(Aptr + k0);
        float4 bv = *(const float4*)(Bptr + (size_t)k0 * N);
        __syncthreads();
        As[acol + 0][arow] = av.x;
        As[acol + 1][arow] = av.y;
        As[acol + 2][arow] = av.z;
        As[acol + 3][arow] = av.w;
        *(float4*)&Bs[brow][bcol] = bv;
        __syncthreads();
#pragma unroll
        for (int kk = 0; kk < 8; kk++) {
            float ra[8], rb[8];
#pragma unroll
            for (int i = 0; i < 8; i++) ra[i] = As[kk][ty + 16 * i];
#pragma unroll
            for (int j = 0; j < 8; j++) rb[j] = Bs[kk][tx + 16 * j];
#pragma unroll
            for (int i = 0; i < 8; i++)
#pragma unroll
                for (int j = 0; j < 8; j++)
                    acc[i][j] = fmaf(ra[i], rb[j], acc[i][j]);
        }
    }

#pragma unroll
    for (int i = 0; i < 8; i++) {
        float* crow = C + (size_t)(bm + ty + 16 * i) * N + bn;
#pragma unroll
        for (int j = 0; j < 8; j++) crow[tx + 16 * j] = acc[i][j];
    }
}

// ---------------------------------------------------------------------------
// RMSNorm (per head, D=128) + RoPE, in place. One warp per (row, head).
// Lane l holds d = l + 32u (u=0..3); rotate_half pairs (d, d+64) are
// (u0,u2) and (u1,u3) within the same lane -> no shuffles for RoPE.
// ---------------------------------------------------------------------------
__global__ void rmsrope_kernel(float* __restrict__ x, const float* __restrict__ w,
                               const float* __restrict__ cosb,
                               const float* __restrict__ sinb, int nh)
{
    const int gwid = (blockIdx.x * blockDim.x + threadIdx.x) >> 5;
    const int lane = threadIdx.x & 31;
    const int total = ROWS * nh;
    if (gwid >= total) return;
    const int row = gwid / nh;
    const int h   = gwid - row * nh;
    const int s   = row & (SS - 1);

    float* xp = x + (size_t)row * (nh * DH) + h * DH;

    float v[4];
#pragma unroll
    for (int u = 0; u < 4; u++) v[u] = xp[lane + 32 * u];

    float ssum = v[0]*v[0] + v[1]*v[1] + v[2]*v[2] + v[3]*v[3];
#pragma unroll
    for (int off = 16; off > 0; off >>= 1)
        ssum += __shfl_xor_sync(0xffffffffu, ssum, off);

    const float r = rsqrtf(ssum * (1.f / DH) + EPS);

    float n[4];
#pragma unroll
    for (int u = 0; u < 4; u++) n[u] = v[u] * r * w[lane + 32 * u];

    const float* cp = cosb + (size_t)s * DH;
    const float* sp = sinb + (size_t)s * DH;
    float c[4], si[4];
#pragma unroll
    for (int u = 0; u < 4; u++) { c[u] = cp[lane + 32 * u]; si[u] = sp[lane + 32 * u]; }

    float o[4];
    o[0] = n[0] * c[0] - n[2] * si[0];
    o[1] = n[1] * c[1] - n[3] * si[1];
    o[2] = n[2] * c[2] + n[0] * si[2];
    o[3] = n[3] * c[3] + n[1] * si[3];

#pragma unroll
    for (int u = 0; u < 4; u++) xp[lane + 32 * u] = o[u];
}

// ---------------------------------------------------------------------------
// Causal GQA flash attention, fp32.
// BM=128 q rows, BN=64 kv rows, D=128. 256 threads: tr=t/16, tc=t%16.
// Thread owns q rows r = tr*8+i (i<8); score cols c = tc+16j (j<4);
// out cols c = tc+16j (j<8). P staged transposed in smem for PV.
// Q layout: [b*S+s][h*128+d]; K/V: [b*S+s][hk*128+d].
// ---------------------------------------------------------------------------
#define FD 132
#define FLASH_SMEM_FLOATS (FD * (128 + 64 + 64 + 64))
#define FLASH_SMEM_BYTES  (FLASH_SMEM_FLOATS * 4)

__global__ __launch_bounds__(256) void flash_kernel(
    const float* __restrict__ Q, const float* __restrict__ K,
    const float* __restrict__ V, float* __restrict__ O)
{
    extern __shared__ float sm[];
    float* Qs = sm;                  // [128][FD]
    float* Ks = Qs + 128 * FD;       // [64][FD]
    float* Vs = Ks + 64 * FD;        // [64][FD]
    float* Ps = Vs + 64 * FD;        // [64][FD] transposed P: [kcol][qrow]

    const int qt = blockIdx.x;       // 0..15
    const int h  = blockIdx.y;       // 0..31
    const int b  = blockIdx.z;       // 0..1
    const int t  = threadIdx.x;
    const int tr = t >> 4;           // 0..15
    const int tc = t & 15;           // 0..15
    const int hk = h >> 3;

    const size_t qbase = ((size_t)(b * SS) + qt * 128) * QCOLS + h * DH;

    // Load Q tile (128 rows x 32 float4)
#pragma unroll
    for (int u = 0; u < 16; u++) {
        int lin = t + u * 256;
        int row = lin >> 5, d4 = lin & 31;
        float4 v = *(const float4*)(Q + qbase + (size_t)row * QCOLS + d4 * 4);
        *(float4*)&Qs[row * FD + d4 * 4] = v;
    }

    float m[8], l[8], acc[8][8];
#pragma unroll
    for (int i = 0; i < 8; i++) {
        m[i] = -1e30f; l[i] = 0.f;
#pragma unroll
        for (int j = 0; j < 8; j++) acc[i][j] = 0.f;
    }

    const int nkt = (qt + 1) * 2;
    for (int kt = 0; kt < nkt; kt++) {
        __syncthreads();
        // Load K,V tiles (64 rows x 32 float4 each)
        const size_t kbase = ((size_t)(b * SS) + kt * 64) * KVCOLS + hk * DH;
#pragma unroll
        for (int u = 0; u < 8; u++) {
            int lin = t + u * 256;
            int row = lin >> 5, d4 = lin & 31;
            *(float4*)&Ks[row * FD + d4 * 4] =
                *(const float4*)(K + kbase + (size_t)row * KVCOLS + d4 * 4);
            *(float4*)&Vs[row * FD + d4 * 4] =
                *(const float4*)(V + kbase + (size_t)row * KVCOLS + d4 * 4);
        }
        __syncthreads();

        // Scores: s[i][j] = Q[r_i] . K[c_j]
        float s[8][4];
#pragma unroll
        for (int i = 0; i < 8; i++)
#pragma unroll
            for (int j = 0; j < 4; j++) s[i][j] = 0.f;

#pragma unroll 4
        for (int k4 = 0; k4 < 32; k4++) {
            float4 qv[8], kv[4];
#pragma unroll
            for (int i = 0; i < 8; i++)
                qv[i] = *(const float4*)&Qs[(tr * 8 + i) * FD + k4 * 4];
#pragma unroll
            for (int j = 0; j < 4; j++)
                kv[j] = *(const float4*)&Ks[(tc + 16 * j) * FD + k4 * 4];
#pragma unroll
            for (int i = 0; i < 8; i++)
#pragma unroll
                for (int j = 0; j < 4; j++) {
                    s[i][j] = fmaf(qv[i].x, kv[j].x, s[i][j]);
                    s[i][j] = fmaf(qv[i].y, kv[j].y, s[i][j]);
                    s[i][j] = fmaf(qv[i].z, kv[j].z, s[i][j]);
                    s[i][j] = fmaf(qv[i].w, kv[j].w, s[i][j]);
                }
        }

        // Scale + causal mask
#pragma unroll
        for (int i = 0; i < 8; i++) {
            const int sq = qt * 128 + tr * 8 + i;
#pragma unroll
            for (int j = 0; j < 4; j++) {
                const int sk = kt * 64 + tc + 16 * j;
                s[i][j] = (sk <= sq) ? s[i][j] * SCALE : -1e30f;
            }
        }

        // Online softmax update (reduce over tc via 16-lane shfl group)
#pragma unroll
        for (int i = 0; i < 8; i++) {
            float mx = fmaxf(fmaxf(s[i][0], s[i][1]), fmaxf(s[i][2], s[i][3]));
#pragma unroll
            for (int off = 8; off > 0; off >>= 1)
                mx = fmaxf(mx, __shfl_xor_sync(0xffffffffu, mx, off));
            const float mn = fmaxf(m[i], mx);
            const float sc = __expf(m[i] - mn);
            float ps = 0.f;
#pragma unroll
            for (int j = 0; j < 4; j++) {
                s[i][j] = __expf(s[i][j] - mn);
                ps += s[i][j];
            }
#pragma unroll
            for (int off = 8; off > 0; off >>= 1)
                ps += __shfl_xor_sync(0xffffffffu, ps, off);
            l[i] = l[i] * sc + ps;
            m[i] = mn;
#pragma unroll
            for (int jj = 0; jj < 8; jj++) acc[i][jj] *= sc;
#pragma unroll
            for (int j = 0; j < 4; j++)
                Ps[(tc + 16 * j) * FD + tr * 8 + i] = s[i][j];
        }
        __syncthreads();

        // PV: acc[r][c] += sum_k P[r][k] * V[k][c]
#pragma unroll 4
        for (int k = 0; k < 64; k++) {
            float4 pv0 = *(const float4*)&Ps[k * FD + tr * 8];
            float4 pv1 = *(const float4*)&Ps[k * FD + tr * 8 + 4];
            float p8[8] = {pv0.x, pv0.y, pv0.z, pv0.w, pv1.x, pv1.y, pv1.z, pv1.w};
            float vv[8];
#pragma unroll
            for (int jj = 0; jj < 8; jj++) vv[jj] = Vs[k * FD + tc + 16 * jj];
#pragma unroll
            for (int i = 0; i < 8; i++)
#pragma unroll
                for (int jj = 0; jj < 8; jj++)
                    acc[i][jj] = fmaf(p8[i], vv[jj], acc[i][jj]);
        }
    }

    // Epilogue: normalize and store
#pragma unroll
    for (int i = 0; i < 8; i++) {
        const float inv = 1.f / l[i];
        float* orow = O + qbase + (size_t)(tr * 8 + i) * QCOLS;
#pragma unroll
        for (int jj = 0; jj < 8; jj++)
            orow[tc + 16 * jj] = acc[i][jj] * inv;
    }
}

// ---------------------------------------------------------------------------
extern "C" void kernel_launch(void* const* d_in, const int* in_sizes, int n_in,
                              void* d_out, int out_size)
{
    const float* hidden = (const float*)d_in[0];
    const float* cosb   = (const float*)d_in[1];
    const float* sinb   = (const float*)d_in[2];
    const float* wq     = (const float*)d_in[3];
    const float* wk     = (const float*)d_in[4];
    const float* wv     = (const float*)d_in[5];
    const float* wo     = (const float*)d_in[6];
    const float* qnw    = (const float*)d_in[7];
    const float* knw    = (const float*)d_in[8];
    float* out = (float*)d_out;

    float *qb, *kb, *vb, *ob;
    cudaGetSymbolAddress((void**)&qb, g_q);
    cudaGetSymbolAddress((void**)&kb, g_k);
    cudaGetSymbolAddress((void**)&vb, g_v);
    cudaGetSymbolAddress((void**)&ob, g_o);

    // QKV projections
    sgemm_kernel<<<dim3(QCOLS / 128, ROWS / 128), 256>>>(hidden, wq, qb, ROWS, QCOLS, HID);
    sgemm_kernel<<<dim3(KVCOLS / 128, ROWS / 128), 256>>>(hidden, wk, kb, ROWS, KVCOLS, HID);
    sgemm_kernel<<<dim3(KVCOLS / 128, ROWS / 128), 256>>>(hidden, wv, vb, ROWS, KVCOLS, HID);

    // RMSNorm + RoPE (q: 4096*32 warps, k: 4096*4 warps; 8 warps/block)
    rmsrope_kernel<<<(ROWS * HQ) / 8, 256>>>(qb, qnw, cosb, sinb, HQ);
    rmsrope_kernel<<<(ROWS * HKV) / 8, 256>>>(kb, knw, cosb, sinb, HKV);

    // Flash attention
    cudaFuncSetAttribute(flash_kernel, cudaFuncAttributeMaxDynamicSharedMemorySize,
                         FLASH_SMEM_BYTES);
    flash_kernel<<<dim3(SS / 128, HQ, BB), 256, FLASH_SMEM_BYTES>>>(qb, kb, vb, ob);

    // Output projection
    sgemm_kernel<<<dim3(HID / 128, ROWS / 128), 256>>>(ob, wo, out, ROWS, HID, QCOLS);
}

// round 7
// speedup vs baseline: 1.8282x; 1.8282x over previous
#include <cuda_runtime.h>
#include <cuda_bf16.h>
#include <cstdint>
#include <math.h>

// Problem constants
#define BB 2
#define SS 2048
#define HID 2048
#define HQ 32
#define HKV 4
#define DH 128
#define ROWS (BB*SS)          // 4096
#define QCOLS (HQ*DH)         // 4096
#define KVCOLS (HKV*DH)       // 512
#define SCALE 0.08838834764831845f
#define EPS 1e-6f

// Scratch (device globals; zero-init BSS, no allocation)
__device__ float g_q[(size_t)ROWS * QCOLS];
__device__ float g_k[(size_t)ROWS * KVCOLS];
__device__ float g_v[(size_t)ROWS * KVCOLS];
__device__ float g_o[(size_t)ROWS * QCOLS];
__device__ float g_a[(size_t)ROWS * HID];        // tf32-rounded hidden
__device__ float g_wqt[(size_t)QCOLS * HID];     // wq^T  [N][K]
__device__ float g_wkt[(size_t)KVCOLS * HID];
__device__ float g_wvt[(size_t)KVCOLS * HID];
__device__ float g_wot[(size_t)HID * QCOLS];     // wo^T

// ---------------------------------------------------------------------------
// Helpers
// ---------------------------------------------------------------------------
__device__ __forceinline__ uint32_t smem_u32(const void* p) {
    uint32_t a;
    asm("{ .reg .u64 t; cvta.to.shared.u64 t, %1; cvt.u32.u64 %0, t; }"
        : "=r"(a) : "l"(p));
    return a;
}

#define CPA16(s, g) \
    asm volatile("cp.async.cg.shared.global [%0], [%1], 16;" :: "r"(s), "l"(g))
#define CPA_COMMIT() asm volatile("cp.async.commit_group;")
#define CPA_WAIT(n)  asm volatile("cp.async.wait_group %0;" :: "n"(n))

__device__ __forceinline__ float rna_tf32(float x) {
    float r; asm("cvt.rna.tf32.f32 %0, %1;" : "=f"(r) : "f"(x)); return r;
}

// m16n8k8 tf32 MMA (baseline PTX, sm_80+): D = A@B + D
__device__ __forceinline__ void mma_tf32(float c[4], const uint32_t a[4],
                                         const uint32_t b[2]) {
    asm volatile(
        "mma.sync.aligned.m16n8k8.row.col.f32.tf32.tf32.f32 "
        "{%0,%1,%2,%3}, {%4,%5,%6,%7}, {%8,%9}, {%0,%1,%2,%3};"
        : "+f"(c[0]), "+f"(c[1]), "+f"(c[2]), "+f"(c[3])
        : "r"(a[0]), "r"(a[1]), "r"(a[2]), "r"(a[3]), "r"(b[0]), "r"(b[1]));
}

// ---------------------------------------------------------------------------
// Elementwise round-to-tf32 copy (in==out allowed). n4 = n/4.
// ---------------------------------------------------------------------------
__global__ void round_copy_kernel(const float* __restrict__ in,
                                  float* __restrict__ out, int n4)
{
    int i = blockIdx.x * blockDim.x + threadIdx.x;
    if (i >= n4) return;
    float4 v = ((const float4*)in)[i];
    v.x = rna_tf32(v.x); v.y = rna_tf32(v.y);
    v.z = rna_tf32(v.z); v.w = rna_tf32(v.w);
    ((float4*)out)[i] = v;
}

// ---------------------------------------------------------------------------
// Transpose + round: in [K][N] row-major -> out [N][K] row-major, tf32-rounded.
// ---------------------------------------------------------------------------
__global__ void transpose_round_kernel(const float* __restrict__ in,
                                       float* __restrict__ out, int K, int N)
{
    __shared__ float tile[32][33];
    const int bx = blockIdx.x * 32;   // N offset
    const int by = blockIdx.y * 32;   // K offset
    const int tx = threadIdx.x, ty = threadIdx.y;
#pragma unroll
    for (int i = 0; i < 32; i += 8)
        tile[ty + i][tx] = in[(size_t)(by + ty + i) * N + bx + tx];
    __syncthreads();
#pragma unroll
    for (int i = 0; i < 32; i += 8)
        out[(size_t)(bx + ty + i) * K + by + tx] = rna_tf32(tile[tx][ty + i]);
}

// ---------------------------------------------------------------------------
// Tensor-core tf32 GEMM: C[M,N] = A[M,K] @ Bt[N,K]^T (row-major fp32/tf32).
// 128x128 CTA tile, BK=32, 256 threads (8 warps: 2m x 4n), warp tile 64x32.
// 3-stage cp.async pipeline. Row stride 36 floats (144B = 9*16B: cp.async-
// aligned AND conflict-free fragment LDS: (36*dr+dc)%32 covers all banks).
// M%128==0, N%128==0, K%32==0.
// ---------------------------------------------------------------------------
#define RS 36
#define NSTAGE 3
#define STAGE_FLOATS (2 * 128 * RS)              // A then B
#define GEMM_SMEM (NSTAGE * STAGE_FLOATS * 4)    // 110592 bytes

__device__ __forceinline__ void load_stage(const float* __restrict__ A,
                                           const float* __restrict__ Bt,
                                           int K, int bm, int bn, int k0,
                                           float* stage, int t)
{
    float* As = stage;
    float* Bs = stage + 128 * RS;
#pragma unroll
    for (int u = 0; u < 4; u++) {
        int id = t + u * 256;
        int row = id >> 3, seg = id & 7;
        CPA16(smem_u32(As + row * RS + seg * 4),
              A + (size_t)(bm + row) * K + k0 + seg * 4);
    }
#pragma unroll
    for (int u = 0; u < 4; u++) {
        int id = t + u * 256;
        int row = id >> 3, seg = id & 7;
        CPA16(smem_u32(Bs + row * RS + seg * 4),
              Bt + (size_t)(bn + row) * K + k0 + seg * 4);
    }
    CPA_COMMIT();
}

__global__ __launch_bounds__(256) void tc_gemm_kernel(
    const float* __restrict__ A, const float* __restrict__ Bt,
    float* __restrict__ C, int M, int N, int K)
{
    extern __shared__ float sm[];
    const int t    = threadIdx.x;
    const int lane = t & 31, wid = t >> 5;
    const int wm   = wid >> 2;       // 0..1
    const int wn   = wid & 3;        // 0..3
    const int bm   = blockIdx.y * 128, bn = blockIdx.x * 128;
    const int qr   = lane >> 2;      // 0..7
    const int qc   = lane & 3;       // 0..3

    float* stg[NSTAGE];
#pragma unroll
    for (int s = 0; s < NSTAGE; s++) stg[s] = sm + s * STAGE_FLOATS;

    float c[4][4][4];
#pragma unroll
    for (int mt = 0; mt < 4; mt++)
#pragma unroll
        for (int nt = 0; nt < 4; nt++)
#pragma unroll
            for (int r = 0; r < 4; r++) c[mt][nt][r] = 0.f;

    const int NIT = K >> 5;
    load_stage(A, Bt, K, bm, bn, 0,  stg[0], t);
    load_stage(A, Bt, K, bm, bn, 32, stg[1], t);

    for (int it = 0; it < NIT; it++) {
        CPA_WAIT(1);
        __syncthreads();
        if (it + 2 < NIT)
            load_stage(A, Bt, K, bm, bn, (it + 2) * 32, stg[(it + 2) % NSTAGE], t);
        else
            CPA_COMMIT();   // empty group keeps wait_group accounting uniform

        const uint32_t* As = (const uint32_t*)stg[it % NSTAGE];
        const uint32_t* Bs = As + 128 * RS;

#pragma unroll
        for (int kk = 0; kk < 4; kk++) {
            uint32_t a[4][4], b[4][2];
            const int kb = kk * 8 + qc;
#pragma unroll
            for (int mt = 0; mt < 4; mt++) {
                const int r = wm * 64 + mt * 16 + qr;
                a[mt][0] = As[r * RS + kb];
                a[mt][1] = As[(r + 8) * RS + kb];
                a[mt][2] = As[r * RS + kb + 4];
                a[mt][3] = As[(r + 8) * RS + kb + 4];
            }
#pragma unroll
            for (int nt = 0; nt < 4; nt++) {
                const int n = wn * 32 + nt * 8 + qr;
                b[nt][0] = Bs[n * RS + kb];
                b[nt][1] = Bs[n * RS + kb + 4];
            }
#pragma unroll
            for (int mt = 0; mt < 4; mt++)
#pragma unroll
                for (int nt = 0; nt < 4; nt++)
                    mma_tf32(c[mt][nt], a[mt], b[nt]);
        }
    }

    // Epilogue: direct fp32 stores (float2 per fragment half-row)
#pragma unroll
    for (int mt = 0; mt < 4; mt++) {
        const int row = bm + wm * 64 + mt * 16 + qr;
#pragma unroll
        for (int nt = 0; nt < 4; nt++) {
            const int col = bn + wn * 32 + nt * 8 + 2 * qc;
            *(float2*)&C[(size_t)row * N + col] =
                make_float2(c[mt][nt][0], c[mt][nt][1]);
            *(float2*)&C[(size_t)(row + 8) * N + col] =
                make_float2(c[mt][nt][2], c[mt][nt][3]);
        }
    }
}

// ---------------------------------------------------------------------------
// RMSNorm (per head, D=128) + RoPE, in place. One warp per (row, head).
// ---------------------------------------------------------------------------
__global__ void rmsrope_kernel(float* __restrict__ x, const float* __restrict__ w,
                               const float* __restrict__ cosb,
                               const float* __restrict__ sinb, int nh)
{
    const int gwid = (blockIdx.x * blockDim.x + threadIdx.x) >> 5;
    const int lane = threadIdx.x & 31;
    const int total = ROWS * nh;
    if (gwid >= total) return;
    const int row = gwid / nh;
    const int h   = gwid - row * nh;
    const int s   = row & (SS - 1);

    float* xp = x + (size_t)row * (nh * DH) + h * DH;

    float v[4];
#pragma unroll
    for (int u = 0; u < 4; u++) v[u] = xp[lane + 32 * u];

    float ssum = v[0]*v[0] + v[1]*v[1] + v[2]*v[2] + v[3]*v[3];
#pragma unroll
    for (int off = 16; off > 0; off >>= 1)
        ssum += __shfl_xor_sync(0xffffffffu, ssum, off);

    const float r = rsqrtf(ssum * (1.f / DH) + EPS);

    float n[4];
#pragma unroll
    for (int u = 0; u < 4; u++) n[u] = v[u] * r * w[lane + 32 * u];

    const float* cp = cosb + (size_t)s * DH;
    const float* sp = sinb + (size_t)s * DH;
    float c[4], si[4];
#pragma unroll
    for (int u = 0; u < 4; u++) { c[u] = cp[lane + 32 * u]; si[u] = sp[lane + 32 * u]; }

    float o[4];
    o[0] = n[0] * c[0] - n[2] * si[0];
    o[1] = n[1] * c[1] - n[3] * si[1];
    o[2] = n[2] * c[2] + n[0] * si[2];
    o[3] = n[3] * c[3] + n[1] * si[3];

#pragma unroll
    for (int u = 0; u < 4; u++) xp[lane + 32 * u] = o[u];
}

// ---------------------------------------------------------------------------
// Causal GQA flash attention, fp32.
// ---------------------------------------------------------------------------
#define FD 132
#define FLASH_SMEM_FLOATS (FD * (128 + 64 + 64 + 64))
#define FLASH_SMEM_BYTES  (FLASH_SMEM_FLOATS * 4)

__global__ __launch_bounds__(256) void flash_kernel(
    const float* __restrict__ Q, const float* __restrict__ K,
    const float* __restrict__ V, float* __restrict__ O)
{
    extern __shared__ float sm[];
    float* Qs = sm;
    float* Ks = Qs + 128 * FD;
    float* Vs = Ks + 64 * FD;
    float* Ps = Vs + 64 * FD;

    const int qt = blockIdx.x;
    const int h  = blockIdx.y;
    const int b  = blockIdx.z;
    const int t  = threadIdx.x;
    const int tr = t >> 4;
    const int tc = t & 15;
    const int hk = h >> 3;

    const size_t qbase = ((size_t)(b * SS) + qt * 128) * QCOLS + h * DH;

#pragma unroll
    for (int u = 0; u < 16; u++) {
        int lin = t + u * 256;
        int row = lin >> 5, d4 = lin & 31;
        float4 v = *(const float4*)(Q + qbase + (size_t)row * QCOLS + d4 * 4);
        *(float4*)&Qs[row * FD + d4 * 4] = v;
    }

    float m[8], l[8], acc[8][8];
#pragma unroll
    for (int i = 0; i < 8; i++) {
        m[i] = -1e30f; l[i] = 0.f;
#pragma unroll
        for (int j = 0; j < 8; j++) acc[i][j] = 0.f;
    }

    const int nkt = (qt + 1) * 2;
    for (int kt = 0; kt < nkt; kt++) {
        __syncthreads();
        const size_t kbase = ((size_t)(b * SS) + kt * 64) * KVCOLS + hk * DH;
#pragma unroll
        for (int u = 0; u < 8; u++) {
            int lin = t + u * 256;
            int row = lin >> 5, d4 = lin & 31;
            *(float4*)&Ks[row * FD + d4 * 4] =
                *(const float4*)(K + kbase + (size_t)row * KVCOLS + d4 * 4);
            *(float4*)&Vs[row * FD + d4 * 4] =
                *(const float4*)(V + kbase + (size_t)row * KVCOLS + d4 * 4);
        }
        __syncthreads();

        float s[8][4];
#pragma unroll
        for (int i = 0; i < 8; i++)
#pragma unroll
            for (int j = 0; j < 4; j++) s[i][j] = 0.f;

#pragma unroll 4
        for (int k4 = 0; k4 < 32; k4++) {
            float4 qv[8], kv[4];
#pragma unroll
            for (int i = 0; i < 8; i++)
                qv[i] = *(const float4*)&Qs[(tr * 8 + i) * FD + k4 * 4];
#pragma unroll
            for (int j = 0; j < 4; j++)
                kv[j] = *(const float4*)&Ks[(tc + 16 * j) * FD + k4 * 4];
#pragma unroll
            for (int i = 0; i < 8; i++)
#pragma unroll
                for (int j = 0; j < 4; j++) {
                    s[i][j] = fmaf(qv[i].x, kv[j].x, s[i][j]);
                    s[i][j] = fmaf(qv[i].y, kv[j].y, s[i][j]);
                    s[i][j] = fmaf(qv[i].z, kv[j].z, s[i][j]);
                    s[i][j] = fmaf(qv[i].w, kv[j].w, s[i][j]);
                }
        }

#pragma unroll
        for (int i = 0; i < 8; i++) {
            const int sq = qt * 128 + tr * 8 + i;
#pragma unroll
            for (int j = 0; j < 4; j++) {
                const int sk = kt * 64 + tc + 16 * j;
                s[i][j] = (sk <= sq) ? s[i][j] * SCALE : -1e30f;
            }
        }

#pragma unroll
        for (int i = 0; i < 8; i++) {
            float mx = fmaxf(fmaxf(s[i][0], s[i][1]), fmaxf(s[i][2], s[i][3]));
#pragma unroll
            for (int off = 8; off > 0; off >>= 1)
                mx = fmaxf(mx, __shfl_xor_sync(0xffffffffu, mx, off));
            const float mn = fmaxf(m[i], mx);
            const float sc = __expf(m[i] - mn);
            float ps = 0.f;
#pragma unroll
            for (int j = 0; j < 4; j++) {
                s[i][j] = __expf(s[i][j] - mn);
                ps += s[i][j];
            }
#pragma unroll
            for (int off = 8; off > 0; off >>= 1)
                ps += __shfl_xor_sync(0xffffffffu, ps, off);
            l[i] = l[i] * sc + ps;
            m[i] = mn;
#pragma unroll
            for (int jj = 0; jj < 8; jj++) acc[i][jj] *= sc;
#pragma unroll
            for (int j = 0; j < 4; j++)
                Ps[(tc + 16 * j) * FD + tr * 8 + i] = s[i][j];
        }
        __syncthreads();

#pragma unroll 4
        for (int k = 0; k < 64; k++) {
            float4 pv0 = *(const float4*)&Ps[k * FD + tr * 8];
            float4 pv1 = *(const float4*)&Ps[k * FD + tr * 8 + 4];
            float p8[8] = {pv0.x, pv0.y, pv0.z, pv0.w, pv1.x, pv1.y, pv1.z, pv1.w};
            float vv[8];
#pragma unroll
            for (int jj = 0; jj < 8; jj++) vv[jj] = Vs[k * FD + tc + 16 * jj];
#pragma unroll
            for (int i = 0; i < 8; i++)
#pragma unroll
                for (int jj = 0; jj < 8; jj++)
                    acc[i][jj] = fmaf(p8[i], vv[jj], acc[i][jj]);
        }
    }

#pragma unroll
    for (int i = 0; i < 8; i++) {
        const float inv = 1.f / l[i];
        float* orow = O + qbase + (size_t)(tr * 8 + i) * QCOLS;
#pragma unroll
        for (int jj = 0; jj < 8; jj++)
            orow[tc + 16 * jj] = acc[i][jj] * inv;
    }
}

// ---------------------------------------------------------------------------
extern "C" void kernel_launch(void* const* d_in, const int* in_sizes, int n_in,
                              void* d_out, int out_size)
{
    const float* hidden = (const float*)d_in[0];
    const float* cosb   = (const float*)d_in[1];
    const float* sinb   = (const float*)d_in[2];
    const float* wq     = (const float*)d_in[3];
    const float* wk     = (const float*)d_in[4];
    const float* wv     = (const float*)d_in[5];
    const float* wo     = (const float*)d_in[6];
    const float* qnw    = (const float*)d_in[7];
    const float* knw    = (const float*)d_in[8];
    float* out = (float*)d_out;

    float *qb, *kb, *vb, *ob, *ab, *wqt, *wkt, *wvt, *wot;
    cudaGetSymbolAddress((void**)&qb,  g_q);
    cudaGetSymbolAddress((void**)&kb,  g_k);
    cudaGetSymbolAddress((void**)&vb,  g_v);
    cudaGetSymbolAddress((void**)&ob,  g_o);
    cudaGetSymbolAddress((void**)&ab,  g_a);
    cudaGetSymbolAddress((void**)&wqt, g_wqt);
    cudaGetSymbolAddress((void**)&wkt, g_wkt);
    cudaGetSymbolAddress((void**)&wvt, g_wvt);
    cudaGetSymbolAddress((void**)&wot, g_wot);

    cudaFuncSetAttribute(tc_gemm_kernel, cudaFuncAttributeMaxDynamicSharedMemorySize,
                         GEMM_SMEM);
    cudaFuncSetAttribute(flash_kernel, cudaFuncAttributeMaxDynamicSharedMemorySize,
                         FLASH_SMEM_BYTES);

    // Round A (hidden) to tf32; transpose+round weights into [N][K]
    round_copy_kernel<<<(ROWS * HID / 4 + 255) / 256, 256>>>(hidden, ab, ROWS * HID / 4);
    transpose_round_kernel<<<dim3(QCOLS / 32, HID / 32), dim3(32, 8)>>>(wq, wqt, HID, QCOLS);
    transpose_round_kernel<<<dim3(KVCOLS / 32, HID / 32), dim3(32, 8)>>>(wk, wkt, HID, KVCOLS);
    transpose_round_kernel<<<dim3(KVCOLS / 32, HID / 32), dim3(32, 8)>>>(wv, wvt, HID, KVCOLS);
    transpose_round_kernel<<<dim3(HID / 32, QCOLS / 32), dim3(32, 8)>>>(wo, wot, QCOLS, HID);

    // QKV projections (tf32 tensor cores)
    tc_gemm_kernel<<<dim3(QCOLS / 128, ROWS / 128), 256, GEMM_SMEM>>>(ab, wqt, qb, ROWS, QCOLS, HID);
    tc_gemm_kernel<<<dim3(KVCOLS / 128, ROWS / 128), 256, GEMM_SMEM>>>(ab, wkt, kb, ROWS, KVCOLS, HID);
    tc_gemm_kernel<<<dim3(KVCOLS / 128, ROWS / 128), 256, GEMM_SMEM>>>(ab, wvt, vb, ROWS, KVCOLS, HID);

    // RMSNorm + RoPE
    rmsrope_kernel<<<(ROWS * HQ) / 8, 256>>>(qb, qnw, cosb, sinb, HQ);
    rmsrope_kernel<<<(ROWS * HKV) / 8, 256>>>(kb, knw, cosb, sinb, HKV);

    // Flash attention (fp32)
    flash_kernel<<<dim3(SS / 128, HQ, BB), 256, FLASH_SMEM_BYTES>>>(qb, kb, vb, ob);

    // Round attention output to tf32, then output projection
    round_copy_kernel<<<(ROWS * QCOLS / 4 + 255) / 256, 256>>>(ob, ob, ROWS * QCOLS / 4);
    tc_gemm_kernel<<<dim3(HID / 128, ROWS / 128), 256, GEMM_SMEM>>>(ob, wot, out, ROWS, HID, QCOLS);
}

// round 8
// speedup vs baseline: 2.6959x; 1.4746x over previous
#include <cuda_runtime.h>
#include <cuda_bf16.h>
#include <cstdint>
#include <math.h>

// Problem constants
#define BB 2
#define SS 2048
#define HID 2048
#define HQ 32
#define HKV 4
#define DH 128
#define ROWS (BB*SS)          // 4096
#define QCOLS (HQ*DH)         // 4096
#define KVCOLS (HKV*DH)       // 512
#define SCALE 0.08838834764831845f
#define EPS 1e-6f

// Scratch (device globals; zero-init BSS, no allocation)
__device__ float g_q[(size_t)ROWS * QCOLS];
__device__ float g_k[(size_t)ROWS * KVCOLS];
__device__ float g_v[(size_t)ROWS * KVCOLS];
__device__ float g_o[(size_t)ROWS * QCOLS];
__device__ float g_a[(size_t)ROWS * HID];        // tf32-rounded hidden
__device__ float g_wqt[(size_t)QCOLS * HID];     // wq^T  [N][K]
__device__ float g_wkt[(size_t)KVCOLS * HID];
__device__ float g_wvt[(size_t)KVCOLS * HID];
__device__ float g_wot[(size_t)HID * QCOLS];     // wo^T

// ---------------------------------------------------------------------------
// Helpers
// ---------------------------------------------------------------------------
__device__ __forceinline__ uint32_t smem_u32(const void* p) {
    uint32_t a;
    asm("{ .reg .u64 t; cvta.to.shared.u64 t, %1; cvt.u32.u64 %0, t; }"
        : "=r"(a) : "l"(p));
    return a;
}

#define CPA16(s, g) \
    asm volatile("cp.async.cg.shared.global [%0], [%1], 16;" :: "r"(s), "l"(g))
#define CPA_COMMIT() asm volatile("cp.async.commit_group;")
#define CPA_WAIT(n)  asm volatile("cp.async.wait_group %0;" :: "n"(n))

__device__ __forceinline__ float rna_tf32(float x) {
    float r; asm("cvt.rna.tf32.f32 %0, %1;" : "=f"(r) : "f"(x)); return r;
}

// m16n8k8 tf32 MMA (baseline PTX, sm_80+): D = A@B + D
__device__ __forceinline__ void mma_tf32(float c[4], const uint32_t a[4],
                                         const uint32_t b[2]) {
    asm volatile(
        "mma.sync.aligned.m16n8k8.row.col.f32.tf32.tf32.f32 "
        "{%0,%1,%2,%3}, {%4,%5,%6,%7}, {%8,%9}, {%0,%1,%2,%3};"
        : "+f"(c[0]), "+f"(c[1]), "+f"(c[2]), "+f"(c[3])
        : "r"(a[0]), "r"(a[1]), "r"(a[2]), "r"(a[3]), "r"(b[0]), "r"(b[1]));
}

// ---------------------------------------------------------------------------
// Elementwise round-to-tf32 copy. n4 = n/4.
// ---------------------------------------------------------------------------
__global__ void round_copy_kernel(const float* __restrict__ in,
                                  float* __restrict__ out, int n4)
{
    int i = blockIdx.x * blockDim.x + threadIdx.x;
    if (i >= n4) return;
    float4 v = ((const float4*)in)[i];
    v.x = rna_tf32(v.x); v.y = rna_tf32(v.y);
    v.z = rna_tf32(v.z); v.w = rna_tf32(v.w);
    ((float4*)out)[i] = v;
}

// ---------------------------------------------------------------------------
// Transpose + round: in [K][N] row-major -> out [N][K] row-major, tf32-rounded.
// ---------------------------------------------------------------------------
__global__ void transpose_round_kernel(const float* __restrict__ in,
                                       float* __restrict__ out, int K, int N)
{
    __shared__ float tile[32][33];
    const int bx = blockIdx.x * 32;   // N offset
    const int by = blockIdx.y * 32;   // K offset
    const int tx = threadIdx.x, ty = threadIdx.y;
#pragma unroll
    for (int i = 0; i < 32; i += 8)
        tile[ty + i][tx] = in[(size_t)(by + ty + i) * N + bx + tx];
    __syncthreads();
#pragma unroll
    for (int i = 0; i < 32; i += 8)
        out[(size_t)(bx + ty + i) * K + by + tx] = rna_tf32(tile[tx][ty + i]);
}

// ---------------------------------------------------------------------------
// Tensor-core tf32 GEMM: C[M,N] = A[M,K] @ Bt[N,K]^T (row-major fp32/tf32).
// 128x128 CTA tile, BK=32, 256 threads (8 warps: 2m x 4n), warp tile 64x32.
// 3-stage cp.async pipeline. Row stride 36 floats.
// ---------------------------------------------------------------------------
#define RS 36
#define NSTAGE 3
#define STAGE_FLOATS (2 * 128 * RS)              // A then B
#define GEMM_SMEM (NSTAGE * STAGE_FLOATS * 4)    // 110592 bytes

__device__ __forceinline__ void load_stage(const float* __restrict__ A,
                                           const float* __restrict__ Bt,
                                           int K, int bm, int bn, int k0,
                                           float* stage, int t)
{
    float* As = stage;
    float* Bs = stage + 128 * RS;
#pragma unroll
    for (int u = 0; u < 4; u++) {
        int id = t + u * 256;
        int row = id >> 3, seg = id & 7;
        CPA16(smem_u32(As + row * RS + seg * 4),
              A + (size_t)(bm + row) * K + k0 + seg * 4);
    }
#pragma unroll
    for (int u = 0; u < 4; u++) {
        int id = t + u * 256;
        int row = id >> 3, seg = id & 7;
        CPA16(smem_u32(Bs + row * RS + seg * 4),
              Bt + (size_t)(bn + row) * K + k0 + seg * 4);
    }
    CPA_COMMIT();
}

__global__ __launch_bounds__(256) void tc_gemm_kernel(
    const float* __restrict__ A, const float* __restrict__ Bt,
    float* __restrict__ C, int M, int N, int K)
{
    extern __shared__ float sm[];
    const int t    = threadIdx.x;
    const int lane = t & 31, wid = t >> 5;
    const int wm   = wid >> 2;       // 0..1
    const int wn   = wid & 3;        // 0..3
    const int bm   = blockIdx.y * 128, bn = blockIdx.x * 128;
    const int qr   = lane >> 2;      // 0..7
    const int qc   = lane & 3;       // 0..3

    float* stg[NSTAGE];
#pragma unroll
    for (int s = 0; s < NSTAGE; s++) stg[s] = sm + s * STAGE_FLOATS;

    float c[4][4][4];
#pragma unroll
    for (int mt = 0; mt < 4; mt++)
#pragma unroll
        for (int nt = 0; nt < 4; nt++)
#pragma unroll
            for (int r = 0; r < 4; r++) c[mt][nt][r] = 0.f;

    const int NIT = K >> 5;
    load_stage(A, Bt, K, bm, bn, 0,  stg[0], t);
    load_stage(A, Bt, K, bm, bn, 32, stg[1], t);

    for (int it = 0; it < NIT; it++) {
        CPA_WAIT(1);
        __syncthreads();
        if (it + 2 < NIT)
            load_stage(A, Bt, K, bm, bn, (it + 2) * 32, stg[(it + 2) % NSTAGE], t);
        else
            CPA_COMMIT();

        const uint32_t* As = (const uint32_t*)stg[it % NSTAGE];
        const uint32_t* Bs = As + 128 * RS;

#pragma unroll
        for (int kk = 0; kk < 4; kk++) {
            uint32_t a[4][4], b[4][2];
            const int kb = kk * 8 + qc;
#pragma unroll
            for (int mt = 0; mt < 4; mt++) {
                const int r = wm * 64 + mt * 16 + qr;
                a[mt][0] = As[r * RS + kb];
                a[mt][1] = As[(r + 8) * RS + kb];
                a[mt][2] = As[r * RS + kb + 4];
                a[mt][3] = As[(r + 8) * RS + kb + 4];
            }
#pragma unroll
            for (int nt = 0; nt < 4; nt++) {
                const int n = wn * 32 + nt * 8 + qr;
                b[nt][0] = Bs[n * RS + kb];
                b[nt][1] = Bs[n * RS + kb + 4];
            }
#pragma unroll
            for (int mt = 0; mt < 4; mt++)
#pragma unroll
                for (int nt = 0; nt < 4; nt++)
                    mma_tf32(c[mt][nt], a[mt], b[nt]);
        }
    }

#pragma unroll
    for (int mt = 0; mt < 4; mt++) {
        const int row = bm + wm * 64 + mt * 16 + qr;
#pragma unroll
        for (int nt = 0; nt < 4; nt++) {
            const int col = bn + wn * 32 + nt * 8 + 2 * qc;
            *(float2*)&C[(size_t)row * N + col] =
                make_float2(c[mt][nt][0], c[mt][nt][1]);
            *(float2*)&C[(size_t)(row + 8) * N + col] =
                make_float2(c[mt][nt][2], c[mt][nt][3]);
        }
    }
}

// ---------------------------------------------------------------------------
// RMSNorm (per head, D=128) + RoPE, in place. One warp per (row, head).
// ---------------------------------------------------------------------------
__global__ void rmsrope_kernel(float* __restrict__ x, const float* __restrict__ w,
                               const float* __restrict__ cosb,
                               const float* __restrict__ sinb, int nh)
{
    const int gwid = (blockIdx.x * blockDim.x + threadIdx.x) >> 5;
    const int lane = threadIdx.x & 31;
    const int total = ROWS * nh;
    if (gwid >= total) return;
    const int row = gwid / nh;
    const int h   = gwid - row * nh;
    const int s   = row & (SS - 1);

    float* xp = x + (size_t)row * (nh * DH) + h * DH;

    float v[4];
#pragma unroll
    for (int u = 0; u < 4; u++) v[u] = xp[lane + 32 * u];

    float ssum = v[0]*v[0] + v[1]*v[1] + v[2]*v[2] + v[3]*v[3];
#pragma unroll
    for (int off = 16; off > 0; off >>= 1)
        ssum += __shfl_xor_sync(0xffffffffu, ssum, off);

    const float r = rsqrtf(ssum * (1.f / DH) + EPS);

    float n[4];
#pragma unroll
    for (int u = 0; u < 4; u++) n[u] = v[u] * r * w[lane + 32 * u];

    const float* cp = cosb + (size_t)s * DH;
    const float* sp = sinb + (size_t)s * DH;
    float c[4], si[4];
#pragma unroll
    for (int u = 0; u < 4; u++) { c[u] = cp[lane + 32 * u]; si[u] = sp[lane + 32 * u]; }

    float o[4];
    o[0] = n[0] * c[0] - n[2] * si[0];
    o[1] = n[1] * c[1] - n[3] * si[1];
    o[2] = n[2] * c[2] + n[0] * si[2];
    o[3] = n[3] * c[3] + n[1] * si[3];

#pragma unroll
    for (int u = 0; u < 4; u++) xp[lane + 32 * u] = o[u];
}

// ---------------------------------------------------------------------------
// Causal GQA flash attention on tf32 tensor cores.
// BM=128, BN=64, D=128. 256 threads = 8 warps; warp wid owns q-rows
// [16*wid, 16*wid+16) -> all row statistics stay inside one warp.
// Smem strides: Q/K/V 132 floats, P 68 floats -> every MMA fragment LDS
// pattern maps lanes to banks (4*qr+qc) mod 32 (conflict-free), except the
// PV B-operand (<=2-way).
// Epilogue stores tf32-rounded output (feeds output projection directly).
// ---------------------------------------------------------------------------
#define FD 132
#define PD 68
#define FL_QS   0
#define FL_KS   (128 * FD)
#define FL_VS   (FL_KS + 64 * FD)
#define FL_PS   (FL_VS + 64 * FD)
#define FLASH_SMEM_BYTES ((FL_PS + 128 * PD) * 4)   // 169984

__global__ __launch_bounds__(256) void flash_tc_kernel(
    const float* __restrict__ Q, const float* __restrict__ K,
    const float* __restrict__ V, float* __restrict__ O)
{
    extern __shared__ float sm[];
    float* Qs = sm + FL_QS;
    float* Ks = sm + FL_KS;
    float* Vs = sm + FL_VS;
    float* Ps = sm + FL_PS;

    const int qt = blockIdx.x;       // 0..15
    const int h  = blockIdx.y;       // 0..31
    const int b  = blockIdx.z;       // 0..1
    const int t  = threadIdx.x;
    const int wid  = t >> 5;
    const int lane = t & 31;
    const int qr = lane >> 2;        // 0..7
    const int qc = lane & 3;         // 0..3
    const int hk = h >> 3;

    const size_t qbase = ((size_t)(b * SS) + qt * 128) * QCOLS + h * DH;

    // Load Q tile (tf32-rounded): 128 rows x 32 float4
#pragma unroll
    for (int u = 0; u < 16; u++) {
        int lin = t + u * 256;
        int row = lin >> 5, d4 = lin & 31;
        float4 v = *(const float4*)(Q + qbase + (size_t)row * QCOLS + d4 * 4);
        v.x = rna_tf32(v.x); v.y = rna_tf32(v.y);
        v.z = rna_tf32(v.z); v.w = rna_tf32(v.w);
        *(float4*)&Qs[row * FD + d4 * 4] = v;
    }

    float oa[16][4];                 // out acc: 16 n8-frags over D=128
#pragma unroll
    for (int nt = 0; nt < 16; nt++)
#pragma unroll
        for (int r = 0; r < 4; r++) oa[nt][r] = 0.f;
    float m0 = -1e30f, m1 = -1e30f, l0 = 0.f, l1 = 0.f;

    const int row0 = qt * 128 + 16 * wid + qr;
    const int row1 = row0 + 8;
    const uint32_t* Qsu = (const uint32_t*)Qs;
    const uint32_t* Ksu = (const uint32_t*)Ks;
    const uint32_t* Vsu = (const uint32_t*)Vs;
    const uint32_t* Psu = (const uint32_t*)Ps;

    const int nkt = (qt + 1) * 2;
    for (int kt = 0; kt < nkt; kt++) {
        __syncthreads();
        const size_t kvb = ((size_t)(b * SS) + kt * 64) * KVCOLS + hk * DH;
#pragma unroll
        for (int u = 0; u < 8; u++) {
            int lin = t + u * 256;
            int row = lin >> 5, d4 = lin & 31;
            float4 kv = *(const float4*)(K + kvb + (size_t)row * KVCOLS + d4 * 4);
            kv.x = rna_tf32(kv.x); kv.y = rna_tf32(kv.y);
            kv.z = rna_tf32(kv.z); kv.w = rna_tf32(kv.w);
            *(float4*)&Ks[row * FD + d4 * 4] = kv;
            float4 vv = *(const float4*)(V + kvb + (size_t)row * KVCOLS + d4 * 4);
            vv.x = rna_tf32(vv.x); vv.y = rna_tf32(vv.y);
            vv.z = rna_tf32(vv.z); vv.w = rna_tf32(vv.w);
            *(float4*)&Vs[row * FD + d4 * 4] = vv;
        }
        __syncthreads();

        // ---- S = Q @ K^T : 16 rows x 64 cols per warp ----
        float s[8][4];
#pragma unroll
        for (int nt = 0; nt < 8; nt++)
#pragma unroll
            for (int r = 0; r < 4; r++) s[nt][r] = 0.f;

#pragma unroll
        for (int ks = 0; ks < 16; ks++) {
            uint32_t a[4], bfr[2];
            const int ab = (16 * wid + qr) * FD + 8 * ks + qc;
            a[0] = Qsu[ab];
            a[1] = Qsu[ab + 8 * FD];
            a[2] = Qsu[ab + 4];
            a[3] = Qsu[ab + 8 * FD + 4];
#pragma unroll
            for (int nt = 0; nt < 8; nt++) {
                const int bb = (8 * nt + qr) * FD + 8 * ks + qc;
                bfr[0] = Ksu[bb];
                bfr[1] = Ksu[bb + 4];
                mma_tf32(s[nt], a, bfr);
            }
        }

        // ---- scale + causal mask + row max ----
        float mx0 = -1e30f, mx1 = -1e30f;
        const int colb = kt * 64 + 2 * qc;
#pragma unroll
        for (int nt = 0; nt < 8; nt++) {
            const int c0 = colb + 8 * nt, c1 = c0 + 1;
            s[nt][0] = (c0 <= row0) ? s[nt][0] * SCALE : -1e30f;
            s[nt][1] = (c1 <= row0) ? s[nt][1] * SCALE : -1e30f;
            s[nt][2] = (c0 <= row1) ? s[nt][2] * SCALE : -1e30f;
            s[nt][3] = (c1 <= row1) ? s[nt][3] * SCALE : -1e30f;
            mx0 = fmaxf(mx0, fmaxf(s[nt][0], s[nt][1]));
            mx1 = fmaxf(mx1, fmaxf(s[nt][2], s[nt][3]));
        }
        mx0 = fmaxf(mx0, __shfl_xor_sync(0xffffffffu, mx0, 1));
        mx0 = fmaxf(mx0, __shfl_xor_sync(0xffffffffu, mx0, 2));
        mx1 = fmaxf(mx1, __shfl_xor_sync(0xffffffffu, mx1, 1));
        mx1 = fmaxf(mx1, __shfl_xor_sync(0xffffffffu, mx1, 2));

        const float mn0 = fmaxf(m0, mx0), mn1 = fmaxf(m1, mx1);
        const float sc0 = __expf(m0 - mn0), sc1 = __expf(m1 - mn1);
        m0 = mn0; m1 = mn1;

        // ---- exp, row sum, stage P (tf32-rounded) ----
        float rs0 = 0.f, rs1 = 0.f;
        const int pb = (16 * wid + qr) * PD + 2 * qc;
#pragma unroll
        for (int nt = 0; nt < 8; nt++) {
            float e0 = __expf(s[nt][0] - mn0);
            float e1 = __expf(s[nt][1] - mn0);
            float e2 = __expf(s[nt][2] - mn1);
            float e3 = __expf(s[nt][3] - mn1);
            rs0 += e0 + e1; rs1 += e2 + e3;
            *(float2*)&Ps[pb + 8 * nt] =
                make_float2(rna_tf32(e0), rna_tf32(e1));
            *(float2*)&Ps[pb + 8 * nt + 8 * PD] =
                make_float2(rna_tf32(e2), rna_tf32(e3));
        }
        rs0 += __shfl_xor_sync(0xffffffffu, rs0, 1);
        rs0 += __shfl_xor_sync(0xffffffffu, rs0, 2);
        rs1 += __shfl_xor_sync(0xffffffffu, rs1, 1);
        rs1 += __shfl_xor_sync(0xffffffffu, rs1, 2);
        l0 = l0 * sc0 + rs0;
        l1 = l1 * sc1 + rs1;

#pragma unroll
        for (int nt = 0; nt < 16; nt++) {
            oa[nt][0] *= sc0; oa[nt][1] *= sc0;
            oa[nt][2] *= sc1; oa[nt][3] *= sc1;
        }
        __syncwarp();

        // ---- O += P @ V : A = P frags (own rows), B = V ----
#pragma unroll
        for (int kv = 0; kv < 8; kv++) {
            uint32_t a[4], bfr[2];
            const int ab = (16 * wid + qr) * PD + 8 * kv + qc;
            a[0] = Psu[ab];
            a[1] = Psu[ab + 8 * PD];
            a[2] = Psu[ab + 4];
            a[3] = Psu[ab + 8 * PD + 4];
#pragma unroll
            for (int nt = 0; nt < 16; nt++) {
                const int bb = (8 * kv + qc) * FD + 8 * nt + qr;
                bfr[0] = Vsu[bb];
                bfr[1] = Vsu[bb + 4 * FD];
                mma_tf32(oa[nt], a, bfr);
            }
        }
        __syncwarp();   // Ps reused next iteration by same warp only, but keep ordering
    }

    // ---- epilogue: normalize, round to tf32, store ----
    const float inv0 = 1.f / l0, inv1 = 1.f / l1;
    float* o0 = (float*)(O + qbase + (size_t)(16 * wid + qr) * QCOLS + 2 * qc);
    float* o1 = (float*)(O + qbase + (size_t)(16 * wid + qr + 8) * QCOLS + 2 * qc);
#pragma unroll
    for (int nt = 0; nt < 16; nt++) {
        *(float2*)(o0 + 8 * nt) = make_float2(rna_tf32(oa[nt][0] * inv0),
                                              rna_tf32(oa[nt][1] * inv0));
        *(float2*)(o1 + 8 * nt) = make_float2(rna_tf32(oa[nt][2] * inv1),
                                              rna_tf32(oa[nt][3] * inv1));
    }
}

// ---------------------------------------------------------------------------
extern "C" void kernel_launch(void* const* d_in, const int* in_sizes, int n_in,
                              void* d_out, int out_size)
{
    const float* hidden = (const float*)d_in[0];
    const float* cosb   = (const float*)d_in[1];
    const float* sinb   = (const float*)d_in[2];
    const float* wq     = (const float*)d_in[3];
    const float* wk     = (const float*)d_in[4];
    const float* wv     = (const float*)d_in[5];
    const float* wo     = (const float*)d_in[6];
    const float* qnw    = (const float*)d_in[7];
    const float* knw    = (const float*)d_in[8];
    float* out = (float*)d_out;

    float *qb, *kb, *vb, *ob, *ab, *wqt, *wkt, *wvt, *wot;
    cudaGetSymbolAddress((void**)&qb,  g_q);
    cudaGetSymbolAddress((void**)&kb,  g_k);
    cudaGetSymbolAddress((void**)&vb,  g_v);
    cudaGetSymbolAddress((void**)&ob,  g_o);
    cudaGetSymbolAddress((void**)&ab,  g_a);
    cudaGetSymbolAddress((void**)&wqt, g_wqt);
    cudaGetSymbolAddress((void**)&wkt, g_wkt);
    cudaGetSymbolAddress((void**)&wvt, g_wvt);
    cudaGetSymbolAddress((void**)&wot, g_wot);

    cudaFuncSetAttribute(tc_gemm_kernel, cudaFuncAttributeMaxDynamicSharedMemorySize,
                         GEMM_SMEM);
    cudaFuncSetAttribute(flash_tc_kernel, cudaFuncAttributeMaxDynamicSharedMemorySize,
                         FLASH_SMEM_BYTES);

    // Round A (hidden) to tf32; transpose+round weights into [N][K]
    round_copy_kernel<<<(ROWS * HID / 4 + 255) / 256, 256>>>(hidden, ab, ROWS * HID / 4);
    transpose_round_kernel<<<dim3(QCOLS / 32, HID / 32), dim3(32, 8)>>>(wq, wqt, HID, QCOLS);
    transpose_round_kernel<<<dim3(KVCOLS / 32, HID / 32), dim3(32, 8)>>>(wk, wkt, HID, KVCOLS);
    transpose_round_kernel<<<dim3(KVCOLS / 32, HID / 32), dim3(32, 8)>>>(wv, wvt, HID, KVCOLS);
    transpose_round_kernel<<<dim3(HID / 32, QCOLS / 32), dim3(32, 8)>>>(wo, wot, QCOLS, HID);

    // QKV projections (tf32 tensor cores)
    tc_gemm_kernel<<<dim3(QCOLS / 128, ROWS / 128), 256, GEMM_SMEM>>>(ab, wqt, qb, ROWS, QCOLS, HID);
    tc_gemm_kernel<<<dim3(KVCOLS / 128, ROWS / 128), 256, GEMM_SMEM>>>(ab, wkt, kb, ROWS, KVCOLS, HID);
    tc_gemm_kernel<<<dim3(KVCOLS / 128, ROWS / 128), 256, GEMM_SMEM>>>(ab, wvt, vb, ROWS, KVCOLS, HID);

    // RMSNorm + RoPE
    rmsrope_kernel<<<(ROWS * HQ) / 8, 256>>>(qb, qnw, cosb, sinb, HQ);
    rmsrope_kernel<<<(ROWS * HKV) / 8, 256>>>(kb, knw, cosb, sinb, HKV);

    // Flash attention (tf32 tensor cores; output stored tf32-rounded)
    flash_tc_kernel<<<dim3(SS / 128, HQ, BB), 256, FLASH_SMEM_BYTES>>>(qb, kb, vb, ob);

    // Output projection
    tc_gemm_kernel<<<dim3(HID / 128, ROWS / 128), 256, GEMM_SMEM>>>(ob, wot, out, ROWS, HID, QCOLS);
}

// round 9
// speedup vs baseline: 2.9713x; 1.1022x over previous
#include <cuda_runtime.h>
#include <cuda_bf16.h>
#include <cstdint>
#include <math.h>

// Problem constants
#define BB 2
#define SS 2048
#define HID 2048
#define HQ 32
#define HKV 4
#define DH 128
#define ROWS (BB*SS)          // 4096
#define QCOLS (HQ*DH)         // 4096
#define KVCOLS (HKV*DH)       // 512
#define SCALE 0.08838834764831845f
#define EPS 1e-6f

// Scratch (device globals; zero-init BSS, no allocation)
__device__ float g_q[(size_t)ROWS * QCOLS];
__device__ float g_k[(size_t)ROWS * KVCOLS];
__device__ float g_v[(size_t)ROWS * KVCOLS];
__device__ float g_o[(size_t)ROWS * QCOLS];
__device__ float g_a[(size_t)ROWS * HID];        // tf32-rounded, k-permuted hidden
__device__ float g_wqt[(size_t)QCOLS * HID];     // wq^T  [N][K], k-permuted
__device__ float g_wkt[(size_t)KVCOLS * HID];
__device__ float g_wvt[(size_t)KVCOLS * HID];
__device__ float g_wot[(size_t)HID * QCOLS];

// ---------------------------------------------------------------------------
// Helpers
// ---------------------------------------------------------------------------
__device__ __forceinline__ uint32_t smem_u32(const void* p) {
    uint32_t a;
    asm("{ .reg .u64 t; cvta.to.shared.u64 t, %1; cvt.u32.u64 %0, t; }"
        : "=r"(a) : "l"(p));
    return a;
}

#define CPA16(s, g) \
    asm volatile("cp.async.cg.shared.global [%0], [%1], 16;" :: "r"(s), "l"(g))
#define CPA_COMMIT() asm volatile("cp.async.commit_group;")
#define CPA_WAIT(n)  asm volatile("cp.async.wait_group %0;" :: "n"(n))

__device__ __forceinline__ float rna_tf32(float x) {
    float r; asm("cvt.rna.tf32.f32 %0, %1;" : "=f"(r) : "f"(x)); return r;
}

// m16n8k8 tf32 MMA (baseline PTX, sm_80+): D = A@B + D
__device__ __forceinline__ void mma_tf32(float c[4], const uint32_t a[4],
                                         const uint32_t b[2]) {
    asm volatile(
        "mma.sync.aligned.m16n8k8.row.col.f32.tf32.tf32.f32 "
        "{%0,%1,%2,%3}, {%4,%5,%6,%7}, {%8,%9}, {%0,%1,%2,%3};"
        : "+f"(c[0]), "+f"(c[1]), "+f"(c[2]), "+f"(c[3])
        : "r"(a[0]), "r"(a[1]), "r"(a[2]), "r"(a[3]), "r"(b[0]), "r"(b[1]));
}

// ---------------------------------------------------------------------------
// Pair-permute + round-to-tf32 copy (in==out allowed).
// Within each 8-float k-group: out[2j]=in[j], out[2j+1]=in[j+4]  (j<4),
// so fragment elements (k, k+4) become adjacent -> LDS.64 in the GEMM.
// n8 = n/8.
// ---------------------------------------------------------------------------
__global__ void perm_round_kernel(const float* __restrict__ in,
                                  float* __restrict__ out, int n8)
{
    int i = blockIdx.x * blockDim.x + threadIdx.x;
    if (i >= n8) return;
    const float4* p = (const float4*)(in + (size_t)8 * i);
    float4 x = p[0], y = p[1];
    float4 w0 = make_float4(rna_tf32(x.x), rna_tf32(y.x),
                            rna_tf32(x.y), rna_tf32(y.y));
    float4 w1 = make_float4(rna_tf32(x.z), rna_tf32(y.z),
                            rna_tf32(x.w), rna_tf32(y.w));
    float4* q = (float4*)(out + (size_t)8 * i);
    q[0] = w0; q[1] = w1;
}

// ---------------------------------------------------------------------------
// Transpose + round + pair-permute: in [K][N] -> out [N][K] (k-permuted).
// ---------------------------------------------------------------------------
__global__ void transpose_round_kernel(const float* __restrict__ in,
                                       float* __restrict__ out, int K, int N)
{
    __shared__ float tile[32][33];
    const int bx = blockIdx.x * 32;   // N offset
    const int by = blockIdx.y * 32;   // K offset
    const int tx = threadIdx.x, ty = threadIdx.y;
#pragma unroll
    for (int i = 0; i < 32; i += 8)
        tile[ty + i][tx] = in[(size_t)(by + ty + i) * N + bx + tx];
    __syncthreads();
    const int j = tx & 7;
    const int kperm = (tx & ~7) + ((j < 4) ? 2 * j : 2 * (j - 4) + 1);
#pragma unroll
    for (int i = 0; i < 32; i += 8)
        out[(size_t)(bx + ty + i) * K + by + kperm] = rna_tf32(tile[tx][ty + i]);
}

// ---------------------------------------------------------------------------
// Tensor-core tf32 GEMM: C[M,N] = A[M,K] @ Bt[N,K]^T, inputs k-permuted.
// 128x128 CTA tile, BK=32, 256 threads (8 warps: 2m x 4n), warp tile 64x32.
// 3-stage cp.async pipeline. Row stride 40 floats (160B, 16B-aligned;
// paired LDS.64 banks (8qr+2qc)%32 conflict-free per phase).
// rnd!=0 -> store C rounded to tf32.
// ---------------------------------------------------------------------------
#define RS 40
#define NSTAGE 3
#define STAGE_FLOATS (2 * 128 * RS)              // A then B
#define GEMM_SMEM (NSTAGE * STAGE_FLOATS * 4)    // 122880 bytes

__device__ __forceinline__ void load_stage(const float* __restrict__ A,
                                           const float* __restrict__ Bt,
                                           int K, int bm, int bn, int k0,
                                           float* stage, int t)
{
    float* As = stage;
    float* Bs = stage + 128 * RS;
#pragma unroll
    for (int u = 0; u < 4; u++) {
        int id = t + u * 256;
        int row = id >> 3, seg = id & 7;
        CPA16(smem_u32(As + row * RS + seg * 4),
              A + (size_t)(bm + row) * K + k0 + seg * 4);
    }
#pragma unroll
    for (int u = 0; u < 4; u++) {
        int id = t + u * 256;
        int row = id >> 3, seg = id & 7;
        CPA16(smem_u32(Bs + row * RS + seg * 4),
              Bt + (size_t)(bn + row) * K + k0 + seg * 4);
    }
    CPA_COMMIT();
}

__global__ __launch_bounds__(256) void tc_gemm_kernel(
    const float* __restrict__ A, const float* __restrict__ Bt,
    float* __restrict__ C, int M, int N, int K, int rnd)
{
    extern __shared__ float sm[];
    const int t    = threadIdx.x;
    const int lane = t & 31, wid = t >> 5;
    const int wm   = wid >> 2;       // 0..1
    const int wn   = wid & 3;        // 0..3
    const int bm   = blockIdx.y * 128, bn = blockIdx.x * 128;
    const int qr   = lane >> 2;      // 0..7
    const int qc   = lane & 3;       // 0..3

    float* stg[NSTAGE];
#pragma unroll
    for (int s = 0; s < NSTAGE; s++) stg[s] = sm + s * STAGE_FLOATS;

    float c[4][4][4];
#pragma unroll
    for (int mt = 0; mt < 4; mt++)
#pragma unroll
        for (int nt = 0; nt < 4; nt++)
#pragma unroll
            for (int r = 0; r < 4; r++) c[mt][nt][r] = 0.f;

    const int NIT = K >> 5;
    load_stage(A, Bt, K, bm, bn, 0,  stg[0], t);
    load_stage(A, Bt, K, bm, bn, 32, stg[1], t);

    for (int it = 0; it < NIT; it++) {
        CPA_WAIT(1);
        __syncthreads();
        if (it + 2 < NIT)
            load_stage(A, Bt, K, bm, bn, (it + 2) * 32, stg[(it + 2) % NSTAGE], t);
        else
            CPA_COMMIT();

        // uint2 view: pair p at float offset 2p
        const uint2* As2 = (const uint2*)stg[it % NSTAGE];
        const uint2* Bs2 = As2 + 64 * RS;        // 128*RS floats = 64*RS uint2

#pragma unroll
        for (int kk = 0; kk < 4; kk++) {
            uint32_t a[4][4], b[4][2];
            const int kp = 4 * kk + qc;          // pair index within row
#pragma unroll
            for (int mt = 0; mt < 4; mt++) {
                const int r = wm * 64 + mt * 16 + qr;
                uint2 p0 = As2[r * (RS / 2) + kp];          // (a0, a2)
                uint2 p1 = As2[(r + 8) * (RS / 2) + kp];    // (a1, a3)
                a[mt][0] = p0.x; a[mt][2] = p0.y;
                a[mt][1] = p1.x; a[mt][3] = p1.y;
            }
#pragma unroll
            for (int nt = 0; nt < 4; nt++) {
                const int n = wn * 32 + nt * 8 + qr;
                uint2 pb = Bs2[n * (RS / 2) + kp];          // (b0, b1)
                b[nt][0] = pb.x; b[nt][1] = pb.y;
            }
#pragma unroll
            for (int mt = 0; mt < 4; mt++)
#pragma unroll
                for (int nt = 0; nt < 4; nt++)
                    mma_tf32(c[mt][nt], a[mt], b[nt]);
        }
    }

#pragma unroll
    for (int mt = 0; mt < 4; mt++) {
        const int row = bm + wm * 64 + mt * 16 + qr;
#pragma unroll
        for (int nt = 0; nt < 4; nt++) {
            const int col = bn + wn * 32 + nt * 8 + 2 * qc;
            float v0 = c[mt][nt][0], v1 = c[mt][nt][1];
            float v2 = c[mt][nt][2], v3 = c[mt][nt][3];
            if (rnd) {
                v0 = rna_tf32(v0); v1 = rna_tf32(v1);
                v2 = rna_tf32(v2); v3 = rna_tf32(v3);
            }
            *(float2*)&C[(size_t)row * N + col] = make_float2(v0, v1);
            *(float2*)&C[(size_t)(row + 8) * N + col] = make_float2(v2, v3);
        }
    }
}

// ---------------------------------------------------------------------------
// RMSNorm (per head, D=128) + RoPE, in place; stores tf32-rounded
// (flash consumes via cp.async, no register pass to round there).
// ---------------------------------------------------------------------------
__global__ void rmsrope_kernel(float* __restrict__ x, const float* __restrict__ w,
                               const float* __restrict__ cosb,
                               const float* __restrict__ sinb, int nh)
{
    const int gwid = (blockIdx.x * blockDim.x + threadIdx.x) >> 5;
    const int lane = threadIdx.x & 31;
    const int total = ROWS * nh;
    if (gwid >= total) return;
    const int row = gwid / nh;
    const int h   = gwid - row * nh;
    const int s   = row & (SS - 1);

    float* xp = x + (size_t)row * (nh * DH) + h * DH;

    float v[4];
#pragma unroll
    for (int u = 0; u < 4; u++) v[u] = xp[lane + 32 * u];

    float ssum = v[0]*v[0] + v[1]*v[1] + v[2]*v[2] + v[3]*v[3];
#pragma unroll
    for (int off = 16; off > 0; off >>= 1)
        ssum += __shfl_xor_sync(0xffffffffu, ssum, off);

    const float r = rsqrtf(ssum * (1.f / DH) + EPS);

    float n[4];
#pragma unroll
    for (int u = 0; u < 4; u++) n[u] = v[u] * r * w[lane + 32 * u];

    const float* cp = cosb + (size_t)s * DH;
    const float* sp = sinb + (size_t)s * DH;
    float c[4], si[4];
#pragma unroll
    for (int u = 0; u < 4; u++) { c[u] = cp[lane + 32 * u]; si[u] = sp[lane + 32 * u]; }

    float o[4];
    o[0] = n[0] * c[0] - n[2] * si[0];
    o[1] = n[1] * c[1] - n[3] * si[1];
    o[2] = n[2] * c[2] + n[0] * si[2];
    o[3] = n[3] * c[3] + n[1] * si[3];

#pragma unroll
    for (int u = 0; u < 4; u++) xp[lane + 32 * u] = rna_tf32(o[u]);
}

// ---------------------------------------------------------------------------
// Causal GQA flash attention, tf32 tensor cores + cp.async pipeline.
// K double-buffered (prefetched one iter ahead); V single-buffered, issued
// at end of iter kt, consumed mid-iter kt+1 (overlaps the S GEMM).
// Group FIFO: per iter exactly one K-group (top) + one V-group (end);
// both waits are wait_group(1). Inputs pre-rounded to tf32 by producers.
// ---------------------------------------------------------------------------
#define FD 132
#define PD 68
#define FQS  0
#define FKS0 (128 * FD)
#define FKS1 (FKS0 + 64 * FD)
#define FVS  (FKS1 + 64 * FD)
#define FPS  (FVS + 64 * FD)
#define FLASH_SMEM_BYTES ((FPS + 128 * PD) * 4)   // 203776

__device__ __forceinline__ void flash_load_kv(const float* __restrict__ base,
                                              float* __restrict__ dst, int t)
{
#pragma unroll
    for (int u = 0; u < 8; u++) {
        int lin = t + u * 256;
        int row = lin >> 5, d4 = lin & 31;
        CPA16(smem_u32(dst + row * FD + d4 * 4),
              base + (size_t)row * KVCOLS + d4 * 4);
    }
}

__global__ __launch_bounds__(256) void flash_tc_kernel(
    const float* __restrict__ Q, const float* __restrict__ K,
    const float* __restrict__ V, float* __restrict__ O)
{
    extern __shared__ float sm[];
    float* Qs = sm + FQS;
    float* Ksb[2] = { sm + FKS0, sm + FKS1 };
    float* Vs = sm + FVS;
    float* Ps = sm + FPS;

    const int qt = blockIdx.x;       // 0..15
    const int h  = blockIdx.y;       // 0..31
    const int b  = blockIdx.z;       // 0..1
    const int t  = threadIdx.x;
    const int wid  = t >> 5;
    const int lane = t & 31;
    const int qr = lane >> 2;        // 0..7
    const int qc = lane & 3;         // 0..3
    const int hk = h >> 3;

    const size_t qbase = ((size_t)(b * SS) + qt * 128) * QCOLS + h * DH;
    const size_t kvrow0 = (size_t)(b * SS) * KVCOLS + hk * DH;
    const int nkt = (qt + 1) * 2;

    // Prologue: group A = Q + K0, group B = V0
#pragma unroll
    for (int u = 0; u < 16; u++) {
        int lin = t + u * 256;
        int row = lin >> 5, d4 = lin & 31;
        CPA16(smem_u32(Qs + row * FD + d4 * 4),
              Q + qbase + (size_t)row * QCOLS + d4 * 4);
    }
    flash_load_kv(K + kvrow0, Ksb[0], t);
    CPA_COMMIT();
    flash_load_kv(V + kvrow0, Vs, t);
    CPA_COMMIT();

    float oa[16][4];
#pragma unroll
    for (int nt = 0; nt < 16; nt++)
#pragma unroll
        for (int r = 0; r < 4; r++) oa[nt][r] = 0.f;
    float m0 = -1e30f, m1 = -1e30f, l0 = 0.f, l1 = 0.f;

    const int row0 = qt * 128 + 16 * wid + qr;
    const int row1 = row0 + 8;
    const uint32_t* Qsu = (const uint32_t*)Qs;
    const uint32_t* Vsu = (const uint32_t*)Vs;
    const uint32_t* Psu = (const uint32_t*)Ps;

    for (int kt = 0; kt < nkt; kt++) {
        CPA_WAIT(1);                 // K(kt) (+Q on kt==0) landed
        __syncthreads();

        // Prefetch K(kt+1) into the other K buffer (overlaps whole iter)
        if (kt + 1 < nkt)
            flash_load_kv(K + kvrow0 + (size_t)(kt + 1) * 64 * KVCOLS,
                          Ksb[(kt + 1) & 1], t);
        CPA_COMMIT();

        const uint32_t* Ksu = (const uint32_t*)Ksb[kt & 1];

        // ---- S = Q @ K^T : 16 rows x 64 cols per warp ----
        float s[8][4];
#pragma unroll
        for (int nt = 0; nt < 8; nt++)
#pragma unroll
            for (int r = 0; r < 4; r++) s[nt][r] = 0.f;

#pragma unroll
        for (int ks = 0; ks < 16; ks++) {
            uint32_t a[4], bfr[2];
            const int ab = (16 * wid + qr) * FD + 8 * ks + qc;
            a[0] = Qsu[ab];
            a[1] = Qsu[ab + 8 * FD];
            a[2] = Qsu[ab + 4];
            a[3] = Qsu[ab + 8 * FD + 4];
#pragma unroll
            for (int nt = 0; nt < 8; nt++) {
                const int bb = (8 * nt + qr) * FD + 8 * ks + qc;
                bfr[0] = Ksu[bb];
                bfr[1] = Ksu[bb + 4];
                mma_tf32(s[nt], a, bfr);
            }
        }

        // ---- scale + causal mask + row max ----
        float mx0 = -1e30f, mx1 = -1e30f;
        const int colb = kt * 64 + 2 * qc;
#pragma unroll
        for (int nt = 0; nt < 8; nt++) {
            const int c0 = colb + 8 * nt, c1 = c0 + 1;
            s[nt][0] = (c0 <= row0) ? s[nt][0] * SCALE : -1e30f;
            s[nt][1] = (c1 <= row0) ? s[nt][1] * SCALE : -1e30f;
            s[nt][2] = (c0 <= row1) ? s[nt][2] * SCALE : -1e30f;
            s[nt][3] = (c1 <= row1) ? s[nt][3] * SCALE : -1e30f;
            mx0 = fmaxf(mx0, fmaxf(s[nt][0], s[nt][1]));
            mx1 = fmaxf(mx1, fmaxf(s[nt][2], s[nt][3]));
        }
        mx0 = fmaxf(mx0, __shfl_xor_sync(0xffffffffu, mx0, 1));
        mx0 = fmaxf(mx0, __shfl_xor_sync(0xffffffffu, mx0, 2));
        mx1 = fmaxf(mx1, __shfl_xor_sync(0xffffffffu, mx1, 1));
        mx1 = fmaxf(mx1, __shfl_xor_sync(0xffffffffu, mx1, 2));

        const float mn0 = fmaxf(m0, mx0), mn1 = fmaxf(m1, mx1);
        const float sc0 = __expf(m0 - mn0), sc1 = __expf(m1 - mn1);
        m0 = mn0; m1 = mn1;

        // ---- exp, row sum, stage P (tf32-rounded) ----
        float rs0 = 0.f, rs1 = 0.f;
        const int pb = (16 * wid + qr) * PD + 2 * qc;
#pragma unroll
        for (int nt = 0; nt < 8; nt++) {
            float e0 = __expf(s[nt][0] - mn0);
            float e1 = __expf(s[nt][1] - mn0);
            float e2 = __expf(s[nt][2] - mn1);
            float e3 = __expf(s[nt][3] - mn1);
            rs0 += e0 + e1; rs1 += e2 + e3;
            *(float2*)&Ps[pb + 8 * nt] =
                make_float2(rna_tf32(e0), rna_tf32(e1));
            *(float2*)&Ps[pb + 8 * nt + 8 * PD] =
                make_float2(rna_tf32(e2), rna_tf32(e3));
        }
        rs0 += __shfl_xor_sync(0xffffffffu, rs0, 1);
        rs0 += __shfl_xor_sync(0xffffffffu, rs0, 2);
        rs1 += __shfl_xor_sync(0xffffffffu, rs1, 1);
        rs1 += __shfl_xor_sync(0xffffffffu, rs1, 2);
        l0 = l0 * sc0 + rs0;
        l1 = l1 * sc1 + rs1;

#pragma unroll
        for (int nt = 0; nt < 16; nt++) {
            oa[nt][0] *= sc0; oa[nt][1] *= sc0;
            oa[nt][2] *= sc1; oa[nt][3] *= sc1;
        }

        CPA_WAIT(1);                 // V(kt) landed (K(kt+1) still in flight)
        __syncthreads();

        // ---- O += P @ V ----
#pragma unroll
        for (int kv = 0; kv < 8; kv++) {
            uint32_t a[4], bfr[2];
            const int ab = (16 * wid + qr) * PD + 8 * kv + qc;
            a[0] = Psu[ab];
            a[1] = Psu[ab + 8 * PD];
            a[2] = Psu[ab + 4];
            a[3] = Psu[ab + 8 * PD + 4];
#pragma unroll
            for (int nt = 0; nt < 16; nt++) {
                const int bb = (8 * kv + qc) * FD + 8 * nt + qr;
                bfr[0] = Vsu[bb];
                bfr[1] = Vsu[bb + 4 * FD];
                mma_tf32(oa[nt], a, bfr);
            }
        }

        __syncthreads();             // all warps done reading V(kt)
        if (kt + 1 < nkt)
            flash_load_kv(V + kvrow0 + (size_t)(kt + 1) * 64 * KVCOLS, Vs, t);
        CPA_COMMIT();
    }

    // ---- epilogue: normalize, round to tf32, store ----
    const float inv0 = 1.f / l0, inv1 = 1.f / l1;
    float* o0 = (float*)(O + qbase + (size_t)(16 * wid + qr) * QCOLS + 2 * qc);
    float* o1 = (float*)(O + qbase + (size_t)(16 * wid + qr + 8) * QCOLS + 2 * qc);
#pragma unroll
    for (int nt = 0; nt < 16; nt++) {
        *(float2*)(o0 + 8 * nt) = make_float2(rna_tf32(oa[nt][0] * inv0),
                                              rna_tf32(oa[nt][1] * inv0));
        *(float2*)(o1 + 8 * nt) = make_float2(rna_tf32(oa[nt][2] * inv1),
                                              rna_tf32(oa[nt][3] * inv1));
    }
}

// ---------------------------------------------------------------------------
extern "C" void kernel_launch(void* const* d_in, const int* in_sizes, int n_in,
                              void* d_out, int out_size)
{
    const float* hidden = (const float*)d_in[0];
    const float* cosb   = (const float*)d_in[1];
    const float* sinb   = (const float*)d_in[2];
    const float* wq     = (const float*)d_in[3];
    const float* wk     = (const float*)d_in[4];
    const float* wv     = (const float*)d_in[5];
    const float* wo     = (const float*)d_in[6];
    const float* qnw    = (const float*)d_in[7];
    const float* knw    = (const float*)d_in[8];
    float* out = (float*)d_out;

    float *qb, *kb, *vb, *ob, *ab, *wqt, *wkt, *wvt, *wot;
    cudaGetSymbolAddress((void**)&qb,  g_q);
    cudaGetSymbolAddress((void**)&kb,  g_k);
    cudaGetSymbolAddress((void**)&vb,  g_v);
    cudaGetSymbolAddress((void**)&ob,  g_o);
    cudaGetSymbolAddress((void**)&ab,  g_a);
    cudaGetSymbolAddress((void**)&wqt, g_wqt);
    cudaGetSymbolAddress((void**)&wkt, g_wkt);
    cudaGetSymbolAddress((void**)&wvt, g_wvt);
    cudaGetSymbolAddress((void**)&wot, g_wot);

    cudaFuncSetAttribute(tc_gemm_kernel, cudaFuncAttributeMaxDynamicSharedMemorySize,
                         GEMM_SMEM);
    cudaFuncSetAttribute(flash_tc_kernel, cudaFuncAttributeMaxDynamicSharedMemorySize,
                         FLASH_SMEM_BYTES);

    // Round+permute A (hidden); transpose+round+permute weights into [N][K]
    perm_round_kernel<<<(ROWS * HID / 8 + 255) / 256, 256>>>(hidden, ab, ROWS * HID / 8);
    transpose_round_kernel<<<dim3(QCOLS / 32, HID / 32), dim3(32, 8)>>>(wq, wqt, HID, QCOLS);
    transpose_round_kernel<<<dim3(KVCOLS / 32, HID / 32), dim3(32, 8)>>>(wk, wkt, HID, KVCOLS);
    transpose_round_kernel<<<dim3(KVCOLS / 32, HID / 32), dim3(32, 8)>>>(wv, wvt, HID, KVCOLS);
    transpose_round_kernel<<<dim3(HID / 32, QCOLS / 32), dim3(32, 8)>>>(wo, wot, QCOLS, HID);

    // QKV projections (tf32 tensor cores); V output rounded for flash cp.async
    tc_gemm_kernel<<<dim3(QCOLS / 128, ROWS / 128), 256, GEMM_SMEM>>>(ab, wqt, qb, ROWS, QCOLS, HID, 0);
    tc_gemm_kernel<<<dim3(KVCOLS / 128, ROWS / 128), 256, GEMM_SMEM>>>(ab, wkt, kb, ROWS, KVCOLS, HID, 0);
    tc_gemm_kernel<<<dim3(KVCOLS / 128, ROWS / 128), 256, GEMM_SMEM>>>(ab, wvt, vb, ROWS, KVCOLS, HID, 1);

    // RMSNorm + RoPE (stores tf32-rounded)
    rmsrope_kernel<<<(ROWS * HQ) / 8, 256>>>(qb, qnw, cosb, sinb, HQ);
    rmsrope_kernel<<<(ROWS * HKV) / 8, 256>>>(kb, knw, cosb, sinb, HKV);

    // Flash attention (tf32 TCs, cp.async pipelined)
    flash_tc_kernel<<<dim3(SS / 128, HQ, BB), 256, FLASH_SMEM_BYTES>>>(qb, kb, vb, ob);

    // Permute attention output k-dim in place, then output projection
    perm_round_kernel<<<(ROWS * QCOLS / 8 + 255) / 256, 256>>>(ob, ob, ROWS * QCOLS / 8);
    tc_gemm_kernel<<<dim3(HID / 128, ROWS / 128), 256, GEMM_SMEM>>>(ob, wot, out, ROWS, HID, QCOLS, 0);
}

// round 11
// speedup vs baseline: 3.4469x; 1.1601x over previous
#include <cuda_runtime.h>
#include <cuda_bf16.h>
#include <cstdint>
#include <math.h>

// Problem constants
#define BB 2
#define SS 2048
#define HID 2048
#define HQ 32
#define HKV 4
#define DH 128
#define ROWS (BB*SS)          // 4096
#define QCOLS (HQ*DH)         // 4096
#define KVCOLS (HKV*DH)       // 512
#define SCALE 0.08838834764831845f
#define EPS 1e-6f

// Scratch (device globals; zero-init BSS, no allocation)
__device__ float g_q[(size_t)ROWS * QCOLS];
__device__ float g_k[(size_t)ROWS * KVCOLS];
__device__ float g_v[(size_t)ROWS * KVCOLS];
__device__ float g_o[(size_t)ROWS * QCOLS];
__device__ float g_a[(size_t)ROWS * HID];        // tf32-rounded, k-permuted hidden
__device__ float g_wqt[(size_t)QCOLS * HID];     // wq^T  [N][K], k-permuted
__device__ float g_wkt[(size_t)KVCOLS * HID];
__device__ float g_wvt[(size_t)KVCOLS * HID];
__device__ float g_wot[(size_t)HID * QCOLS];

// ---------------------------------------------------------------------------
// Helpers
// ---------------------------------------------------------------------------
__device__ __forceinline__ uint32_t smem_u32(const void* p) {
    uint32_t a;
    asm("{ .reg .u64 t; cvta.to.shared.u64 t, %1; cvt.u32.u64 %0, t; }"
        : "=r"(a) : "l"(p));
    return a;
}

#define CPA16(s, g) \
    asm volatile("cp.async.cg.shared.global [%0], [%1], 16;" :: "r"(s), "l"(g))
#define CPA_COMMIT() asm volatile("cp.async.commit_group;")
#define CPA_WAIT(n)  asm volatile("cp.async.wait_group %0;" :: "n"(n))

__device__ __forceinline__ float rna_tf32(float x) {
    float r; asm("cvt.rna.tf32.f32 %0, %1;" : "=f"(r) : "f"(x)); return r;
}

// m16n8k8 tf32 MMA (baseline PTX, sm_80+): D = A@B + D
__device__ __forceinline__ void mma_tf32(float c[4], const uint32_t a[4],
                                         const uint32_t b[2]) {
    asm volatile(
        "mma.sync.aligned.m16n8k8.row.col.f32.tf32.tf32.f32 "
        "{%0,%1,%2,%3}, {%4,%5,%6,%7}, {%8,%9}, {%0,%1,%2,%3};"
        : "+f"(c[0]), "+f"(c[1]), "+f"(c[2]), "+f"(c[3])
        : "r"(a[0]), "r"(a[1]), "r"(a[2]), "r"(a[3]), "r"(b[0]), "r"(b[1]));
}

// ---------------------------------------------------------------------------
// Pair-permute + round-to-tf32 copy (in==out allowed).
// Within each 8-float k-group: out[2j]=in[j], out[2j+1]=in[j+4]  (j<4).
// ---------------------------------------------------------------------------
__global__ void perm_round_kernel(const float* __restrict__ in,
                                  float* __restrict__ out, int n8)
{
    int i = blockIdx.x * blockDim.x + threadIdx.x;
    if (i >= n8) return;
    const float4* p = (const float4*)(in + (size_t)8 * i);
    float4 x = p[0], y = p[1];
    float4 w0 = make_float4(rna_tf32(x.x), rna_tf32(y.x),
                            rna_tf32(x.y), rna_tf32(y.y));
    float4 w1 = make_float4(rna_tf32(x.z), rna_tf32(y.z),
                            rna_tf32(x.w), rna_tf32(y.w));
    float4* q = (float4*)(out + (size_t)8 * i);
    q[0] = w0; q[1] = w1;
}

// ---------------------------------------------------------------------------
// Transpose + round + pair-permute: in [K][N] -> out [N][K] (k-permuted).
// ---------------------------------------------------------------------------
__global__ void transpose_round_kernel(const float* __restrict__ in,
                                       float* __restrict__ out, int K, int N)
{
    __shared__ float tile[32][33];
    const int bx = blockIdx.x * 32;   // N offset
    const int by = blockIdx.y * 32;   // K offset
    const int tx = threadIdx.x, ty = threadIdx.y;
#pragma unroll
    for (int i = 0; i < 32; i += 8)
        tile[ty + i][tx] = in[(size_t)(by + ty + i) * N + bx + tx];
    __syncthreads();
    const int j = tx & 7;
    const int kperm = (tx & ~7) + ((j < 4) ? 2 * j : 2 * (j - 4) + 1);
#pragma unroll
    for (int i = 0; i < 32; i += 8)
        out[(size_t)(bx + ty + i) * K + by + kperm] = rna_tf32(tile[tx][ty + i]);
}

// ---------------------------------------------------------------------------
// tf32 GEMM, 128x128 CTA tile (used for the narrow KV projections).
// Inputs k-permuted. rnd!=0 -> store rounded to tf32.
// ---------------------------------------------------------------------------
#define RS 40
#define NSTAGE 3
#define STAGE_FLOATS (2 * 128 * RS)
#define GEMM_SMEM (NSTAGE * STAGE_FLOATS * 4)    // 122880

__device__ __forceinline__ void load_stage(const float* __restrict__ A,
                                           const float* __restrict__ Bt,
                                           int K, int bm, int bn, int k0,
                                           float* stage, int t)
{
    float* As = stage;
    float* Bs = stage + 128 * RS;
#pragma unroll
    for (int u = 0; u < 4; u++) {
        int id = t + u * 256;
        int row = id >> 3, seg = id & 7;
        CPA16(smem_u32(As + row * RS + seg * 4),
              A + (size_t)(bm + row) * K + k0 + seg * 4);
    }
#pragma unroll
    for (int u = 0; u < 4; u++) {
        int id = t + u * 256;
        int row = id >> 3, seg = id & 7;
        CPA16(smem_u32(Bs + row * RS + seg * 4),
              Bt + (size_t)(bn + row) * K + k0 + seg * 4);
    }
    CPA_COMMIT();
}

__global__ __launch_bounds__(256) void tc_gemm_kernel(
    const float* __restrict__ A, const float* __restrict__ Bt,
    float* __restrict__ C, int M, int N, int K, int rnd)
{
    extern __shared__ float sm[];
    const int t    = threadIdx.x;
    const int lane = t & 31, wid = t >> 5;
    const int wm   = wid >> 2;
    const int wn   = wid & 3;
    const int bm   = blockIdx.y * 128, bn = blockIdx.x * 128;
    const int qr   = lane >> 2;
    const int qc   = lane & 3;

    float* stg[NSTAGE];
#pragma unroll
    for (int s = 0; s < NSTAGE; s++) stg[s] = sm + s * STAGE_FLOATS;

    float c[4][4][4];
#pragma unroll
    for (int mt = 0; mt < 4; mt++)
#pragma unroll
        for (int nt = 0; nt < 4; nt++)
#pragma unroll
            for (int r = 0; r < 4; r++) c[mt][nt][r] = 0.f;

    const int NIT = K >> 5;
    load_stage(A, Bt, K, bm, bn, 0,  stg[0], t);
    load_stage(A, Bt, K, bm, bn, 32, stg[1], t);

    for (int it = 0; it < NIT; it++) {
        CPA_WAIT(1);
        __syncthreads();
        if (it + 2 < NIT)
            load_stage(A, Bt, K, bm, bn, (it + 2) * 32, stg[(it + 2) % NSTAGE], t);
        else
            CPA_COMMIT();

        const uint2* As2 = (const uint2*)stg[it % NSTAGE];
        const uint2* Bs2 = As2 + 64 * RS;

#pragma unroll
        for (int kk = 0; kk < 4; kk++) {
            uint32_t a[4][4], b[4][2];
            const int kp = 4 * kk + qc;
#pragma unroll
            for (int mt = 0; mt < 4; mt++) {
                const int r = wm * 64 + mt * 16 + qr;
                uint2 p0 = As2[r * (RS / 2) + kp];
                uint2 p1 = As2[(r + 8) * (RS / 2) + kp];
                a[mt][0] = p0.x; a[mt][2] = p0.y;
                a[mt][1] = p1.x; a[mt][3] = p1.y;
            }
#pragma unroll
            for (int nt = 0; nt < 4; nt++) {
                const int n = wn * 32 + nt * 8 + qr;
                uint2 pb = Bs2[n * (RS / 2) + kp];
                b[nt][0] = pb.x; b[nt][1] = pb.y;
            }
#pragma unroll
            for (int mt = 0; mt < 4; mt++)
#pragma unroll
                for (int nt = 0; nt < 4; nt++)
                    mma_tf32(c[mt][nt], a[mt], b[nt]);
        }
    }

#pragma unroll
    for (int mt = 0; mt < 4; mt++) {
        const int row = bm + wm * 64 + mt * 16 + qr;
#pragma unroll
        for (int nt = 0; nt < 4; nt++) {
            const int col = bn + wn * 32 + nt * 8 + 2 * qc;
            float v0 = c[mt][nt][0], v1 = c[mt][nt][1];
            float v2 = c[mt][nt][2], v3 = c[mt][nt][3];
            if (rnd) {
                v0 = rna_tf32(v0); v1 = rna_tf32(v1);
                v2 = rna_tf32(v2); v3 = rna_tf32(v3);
            }
            *(float2*)&C[(size_t)row * N + col] = make_float2(v0, v1);
            *(float2*)&C[(size_t)(row + 8) * N + col] = make_float2(v2, v3);
        }
    }
}

// ---------------------------------------------------------------------------
// tf32 GEMM, 128x256 CTA tile (warp tile 64x64) for the big GEMMs.
// Halves A-side L2 refill traffic; LDS/MMA ratio 0.5.
// ---------------------------------------------------------------------------
#define STAGE256_FLOATS ((128 + 256) * RS)            // 15360 floats
#define GEMM256_SMEM (NSTAGE * STAGE256_FLOATS * 4)   // 184320 bytes

__device__ __forceinline__ void load_stage256(const float* __restrict__ A,
                                              const float* __restrict__ Bt,
                                              int K, int bm, int bn, int k0,
                                              float* stage, int t)
{
    float* As = stage;
    float* Bs = stage + 128 * RS;
#pragma unroll
    for (int u = 0; u < 4; u++) {
        int id = t + u * 256;
        int row = id >> 3, seg = id & 7;
        CPA16(smem_u32(As + row * RS + seg * 4),
              A + (size_t)(bm + row) * K + k0 + seg * 4);
    }
#pragma unroll
    for (int u = 0; u < 8; u++) {
        int id = t + u * 256;
        int row = id >> 3, seg = id & 7;
        CPA16(smem_u32(Bs + row * RS + seg * 4),
              Bt + (size_t)(bn + row) * K + k0 + seg * 4);
    }
    CPA_COMMIT();
}

__global__ __launch_bounds__(256) void tc_gemm256_kernel(
    const float* __restrict__ A, const float* __restrict__ Bt,
    float* __restrict__ C, int M, int N, int K)
{
    extern __shared__ float sm[];
    const int t    = threadIdx.x;
    const int lane = t & 31, wid = t >> 5;
    const int wm   = wid >> 2;       // 0..1
    const int wn   = wid & 3;        // 0..3
    const int bm   = blockIdx.y * 128, bn = blockIdx.x * 256;
    const int qr   = lane >> 2;
    const int qc   = lane & 3;

    float* stg[NSTAGE];
#pragma unroll
    for (int s = 0; s < NSTAGE; s++) stg[s] = sm + s * STAGE256_FLOATS;

    float c[4][8][4];
#pragma unroll
    for (int mt = 0; mt < 4; mt++)
#pragma unroll
        for (int nt = 0; nt < 8; nt++)
#pragma unroll
            for (int r = 0; r < 4; r++) c[mt][nt][r] = 0.f;

    const int NIT = K >> 5;
    load_stage256(A, Bt, K, bm, bn, 0,  stg[0], t);
    load_stage256(A, Bt, K, bm, bn, 32, stg[1], t);

    for (int it = 0; it < NIT; it++) {
        CPA_WAIT(1);
        __syncthreads();
        if (it + 2 < NIT)
            load_stage256(A, Bt, K, bm, bn, (it + 2) * 32, stg[(it + 2) % NSTAGE], t);
        else
            CPA_COMMIT();

        const uint2* As2 = (const uint2*)stg[it % NSTAGE];
        const uint2* Bs2 = As2 + 64 * RS;            // 128*RS floats

#pragma unroll
        for (int kk = 0; kk < 4; kk++) {
            uint32_t a[4][4], b[8][2];
            const int kp = 4 * kk + qc;
#pragma unroll
            for (int mt = 0; mt < 4; mt++) {
                const int r = wm * 64 + mt * 16 + qr;
                uint2 p0 = As2[r * (RS / 2) + kp];
                uint2 p1 = As2[(r + 8) * (RS / 2) + kp];
                a[mt][0] = p0.x; a[mt][2] = p0.y;
                a[mt][1] = p1.x; a[mt][3] = p1.y;
            }
#pragma unroll
            for (int nt = 0; nt < 8; nt++) {
                const int n = wn * 64 + nt * 8 + qr;
                uint2 pb = Bs2[n * (RS / 2) + kp];
                b[nt][0] = pb.x; b[nt][1] = pb.y;
            }
#pragma unroll
            for (int mt = 0; mt < 4; mt++)
#pragma unroll
                for (int nt = 0; nt < 8; nt++)
                    mma_tf32(c[mt][nt], a[mt], b[nt]);
        }
    }

#pragma unroll
    for (int mt = 0; mt < 4; mt++) {
        const int row = bm + wm * 64 + mt * 16 + qr;
#pragma unroll
        for (int nt = 0; nt < 8; nt++) {
            const int col = bn + wn * 64 + nt * 8 + 2 * qc;
            *(float2*)&C[(size_t)row * N + col] =
                make_float2(c[mt][nt][0], c[mt][nt][1]);
            *(float2*)&C[(size_t)(row + 8) * N + col] =
                make_float2(c[mt][nt][2], c[mt][nt][3]);
        }
    }
}

// ---------------------------------------------------------------------------
// RMSNorm + RoPE, in place; stores tf32-rounded AND k-pair-permuted
// (flash reads Q/K fragments as LDS.64 pairs).
// ---------------------------------------------------------------------------
__global__ void rmsrope_kernel(float* __restrict__ x, const float* __restrict__ w,
                               const float* __restrict__ cosb,
                               const float* __restrict__ sinb, int nh)
{
    const int gwid = (blockIdx.x * blockDim.x + threadIdx.x) >> 5;
    const int lane = threadIdx.x & 31;
    const int total = ROWS * nh;
    if (gwid >= total) return;
    const int row = gwid / nh;
    const int h   = gwid - row * nh;
    const int s   = row & (SS - 1);

    float* xp = x + (size_t)row * (nh * DH) + h * DH;

    float v[4];
#pragma unroll
    for (int u = 0; u < 4; u++) v[u] = xp[lane + 32 * u];

    float ssum = v[0]*v[0] + v[1]*v[1] + v[2]*v[2] + v[3]*v[3];
#pragma unroll
    for (int off = 16; off > 0; off >>= 1)
        ssum += __shfl_xor_sync(0xffffffffu, ssum, off);

    const float r = rsqrtf(ssum * (1.f / DH) + EPS);

    float n[4];
#pragma unroll
    for (int u = 0; u < 4; u++) n[u] = v[u] * r * w[lane + 32 * u];

    const float* cp = cosb + (size_t)s * DH;
    const float* sp = sinb + (size_t)s * DH;
    float c[4], si[4];
#pragma unroll
    for (int u = 0; u < 4; u++) { c[u] = cp[lane + 32 * u]; si[u] = sp[lane + 32 * u]; }

    float o[4];
    o[0] = n[0] * c[0] - n[2] * si[0];
    o[1] = n[1] * c[1] - n[3] * si[1];
    o[2] = n[2] * c[2] + n[0] * si[2];
    o[3] = n[3] * c[3] + n[1] * si[3];

    const int j  = lane & 7;
    const int wi = (lane & ~7) + ((j < 4) ? 2 * j : 2 * (j - 4) + 1);
#pragma unroll
    for (int u = 0; u < 4; u++) xp[wi + 32 * u] = rna_tf32(o[u]);
}

// ---------------------------------------------------------------------------
// Causal GQA flash attention, tf32 TCs + cp.async pipeline.
// Q/K stored k-permuted by rmsrope -> S-GEMM fragments are LDS.64 pairs.
// P staged permuted -> PV A-fragments pair. FD=136: V B-operand loads are
// fully conflict-free; paired loads clean 2-phase.
// Epilogue writes permuted+rounded output (feeds O-proj directly).
// ---------------------------------------------------------------------------
#define FD 136
#define PD 72
#define FQS  0
#define FKS0 (128 * FD)
#define FKS1 (FKS0 + 64 * FD)
#define FVS  (FKS1 + 64 * FD)
#define FPS  (FVS + 64 * FD)
#define FLASH_SMEM_BYTES ((FPS + 128 * PD) * 4)   // 210944

__device__ __forceinline__ void flash_load_kv(const float* __restrict__ base,
                                              float* __restrict__ dst, int t)
{
#pragma unroll
    for (int u = 0; u < 8; u++) {
        int lin = t + u * 256;
        int row = lin >> 5, d4 = lin & 31;
        CPA16(smem_u32(dst + row * FD + d4 * 4),
              base + (size_t)row * KVCOLS + d4 * 4);
    }
}

__global__ __launch_bounds__(256) void flash_tc_kernel(
    const float* __restrict__ Q, const float* __restrict__ K,
    const float* __restrict__ V, float* __restrict__ O)
{
    extern __shared__ float sm[];
    float* Qs = sm + FQS;
    float* Ksb[2] = { sm + FKS0, sm + FKS1 };
    float* Vs = sm + FVS;
    float* Ps = sm + FPS;

    const int qt = blockIdx.x;
    const int h  = blockIdx.y;
    const int b  = blockIdx.z;
    const int t  = threadIdx.x;
    const int wid  = t >> 5;
    const int lane = t & 31;
    const int qr = lane >> 2;
    const int qc = lane & 3;
    const int hk = h >> 3;

    const size_t qbase = ((size_t)(b * SS) + qt * 128) * QCOLS + h * DH;
    const size_t kvrow0 = (size_t)(b * SS) * KVCOLS + hk * DH;
    const int nkt = (qt + 1) * 2;

    // Prologue: group A = Q + K0, group B = V0
#pragma unroll
    for (int u = 0; u < 16; u++) {
        int lin = t + u * 256;
        int row = lin >> 5, d4 = lin & 31;
        CPA16(smem_u32(Qs + row * FD + d4 * 4),
              Q + qbase + (size_t)row * QCOLS + d4 * 4);
    }
    flash_load_kv(K + kvrow0, Ksb[0], t);
    CPA_COMMIT();
    flash_load_kv(V + kvrow0, Vs, t);
    CPA_COMMIT();

    float oa[16][4];
#pragma unroll
    for (int nt = 0; nt < 16; nt++)
#pragma unroll
        for (int r = 0; r < 4; r++) oa[nt][r] = 0.f;
    float m0 = -1e30f, m1 = -1e30f, l0 = 0.f, l1 = 0.f;

    const int row0 = qt * 128 + 16 * wid + qr;
    const int row1 = row0 + 8;
    const uint2* Qs2 = (const uint2*)Qs;
    const uint32_t* Vsu = (const uint32_t*)Vs;
    const uint2* Ps2 = (const uint2*)Ps;
    // permuted position of score col 2qc within its 8-group
    const int pos0 = (qc < 2) ? 4 * qc : 4 * qc - 7;

    for (int kt = 0; kt < nkt; kt++) {
        CPA_WAIT(1);
        __syncthreads();

        if (kt + 1 < nkt)
            flash_load_kv(K + kvrow0 + (size_t)(kt + 1) * 64 * KVCOLS,
                          Ksb[(kt + 1) & 1], t);
        CPA_COMMIT();

        const uint2* Ks2 = (const uint2*)Ksb[kt & 1];

        // ---- S = Q @ K^T : paired fragment loads (LDS.64) ----
        float s[8][4];
#pragma unroll
        for (int nt = 0; nt < 8; nt++)
#pragma unroll
            for (int r = 0; r < 4; r++) s[nt][r] = 0.f;

#pragma unroll
        for (int ks = 0; ks < 16; ks++) {
            uint32_t a[4], bfr[2];
            const int ab = (16 * wid + qr) * (FD / 2) + 4 * ks + qc;
            uint2 p0 = Qs2[ab];
            uint2 p1 = Qs2[ab + 8 * (FD / 2)];
            a[0] = p0.x; a[2] = p0.y;
            a[1] = p1.x; a[3] = p1.y;
#pragma unroll
            for (int nt = 0; nt < 8; nt++) {
                uint2 pb = Ks2[(8 * nt + qr) * (FD / 2) + 4 * ks + qc];
                bfr[0] = pb.x; bfr[1] = pb.y;
                mma_tf32(s[nt], a, bfr);
            }
        }

        // ---- scale + causal mask + row max ----
        float mx0 = -1e30f, mx1 = -1e30f;
        const int colb = kt * 64 + 2 * qc;
#pragma unroll
        for (int nt = 0; nt < 8; nt++) {
            const int c0 = colb + 8 * nt, c1 = c0 + 1;
            s[nt][0] = (c0 <= row0) ? s[nt][0] * SCALE : -1e30f;
            s[nt][1] = (c1 <= row0) ? s[nt][1] * SCALE : -1e30f;
            s[nt][2] = (c0 <= row1) ? s[nt][2] * SCALE : -1e30f;
            s[nt][3] = (c1 <= row1) ? s[nt][3] * SCALE : -1e30f;
            mx0 = fmaxf(mx0, fmaxf(s[nt][0], s[nt][1]));
            mx1 = fmaxf(mx1, fmaxf(s[nt][2], s[nt][3]));
        }
        mx0 = fmaxf(mx0, __shfl_xor_sync(0xffffffffu, mx0, 1));
        mx0 = fmaxf(mx0, __shfl_xor_sync(0xffffffffu, mx0, 2));
        mx1 = fmaxf(mx1, __shfl_xor_sync(0xffffffffu, mx1, 1));
        mx1 = fmaxf(mx1, __shfl_xor_sync(0xffffffffu, mx1, 2));

        const float mn0 = fmaxf(m0, mx0), mn1 = fmaxf(m1, mx1);
        const float sc0 = __expf(m0 - mn0), sc1 = __expf(m1 - mn1);
        m0 = mn0; m1 = mn1;

        // ---- exp, row sum, stage P in permuted order ----
        float rs0 = 0.f, rs1 = 0.f;
        const int pr0 = (16 * wid + qr) * PD;
        const int pr1 = pr0 + 8 * PD;
#pragma unroll
        for (int nt = 0; nt < 8; nt++) {
            float e0 = __expf(s[nt][0] - mn0);
            float e1 = __expf(s[nt][1] - mn0);
            float e2 = __expf(s[nt][2] - mn1);
            float e3 = __expf(s[nt][3] - mn1);
            rs0 += e0 + e1; rs1 += e2 + e3;
            Ps[pr0 + 8 * nt + pos0]     = rna_tf32(e0);
            Ps[pr0 + 8 * nt + pos0 + 2] = rna_tf32(e1);
            Ps[pr1 + 8 * nt + pos0]     = rna_tf32(e2);
            Ps[pr1 + 8 * nt + pos0 + 2] = rna_tf32(e3);
        }
        rs0 += __shfl_xor_sync(0xffffffffu, rs0, 1);
        rs0 += __shfl_xor_sync(0xffffffffu, rs0, 2);
        rs1 += __shfl_xor_sync(0xffffffffu, rs1, 1);
        rs1 += __shfl_xor_sync(0xffffffffu, rs1, 2);
        l0 = l0 * sc0 + rs0;
        l1 = l1 * sc1 + rs1;

#pragma unroll
        for (int nt = 0; nt < 16; nt++) {
            oa[nt][0] *= sc0; oa[nt][1] *= sc0;
            oa[nt][2] *= sc1; oa[nt][3] *= sc1;
        }

        CPA_WAIT(1);
        __syncthreads();

        // ---- O += P @ V : paired P loads, conflict-free V loads ----
#pragma unroll
        for (int kv = 0; kv < 8; kv++) {
            uint32_t a[4], bfr[2];
            const int ab = (16 * wid + qr) * (PD / 2) + 4 * kv + qc;
            uint2 p0 = Ps2[ab];
            uint2 p1 = Ps2[ab + 8 * (PD / 2)];
            a[0] = p0.x; a[2] = p0.y;
            a[1] = p1.x; a[3] = p1.y;
#pragma unroll
            for (int nt = 0; nt < 16; nt++) {
                const int bb = (8 * kv + qc) * FD + 8 * nt + qr;
                bfr[0] = Vsu[bb];
                bfr[1] = Vsu[bb + 4 * FD];
                mma_tf32(oa[nt], a, bfr);
            }
        }

        __syncthreads();
        if (kt + 1 < nkt)
            flash_load_kv(V + kvrow0 + (size_t)(kt + 1) * 64 * KVCOLS, Vs, t);
        CPA_COMMIT();
    }

    // ---- epilogue: normalize, round, store k-PERMUTED (feeds O-proj) ----
    const float inv0 = 1.f / l0, inv1 = 1.f / l1;
    float* o0 = (float*)(O + qbase + (size_t)(16 * wid + qr) * QCOLS);
    float* o1 = (float*)(O + qbase + (size_t)(16 * wid + qr + 8) * QCOLS);
#pragma unroll
    for (int nt = 0; nt < 16; nt++) {
        o0[8 * nt + pos0]     = rna_tf32(oa[nt][0] * inv0);
        o0[8 * nt + pos0 + 2] = rna_tf32(oa[nt][1] * inv0);
        o1[8 * nt + pos0]     = rna_tf32(oa[nt][2] * inv1);
        o1[8 * nt + pos0 + 2] = rna_tf32(oa[nt][3] * inv1);
    }
}

// ---------------------------------------------------------------------------
extern "C" void kernel_launch(void* const* d_in, const int* in_sizes, int n_in,
                              void* d_out, int out_size)
{
    const float* hidden = (const float*)d_in[0];
    const float* cosb   = (const float*)d_in[1];
    const float* sinb   = (const float*)d_in[2];
    const float* wq     = (const float*)d_in[3];
    const float* wk     = (const float*)d_in[4];
    const float* wv     = (const float*)d_in[5];
    const float* wo     = (const float*)d_in[6];
    const float* qnw    = (const float*)d_in[7];
    const float* knw    = (const float*)d_in[8];
    float* out = (float*)d_out;

    float *qb, *kb, *vb, *ob, *ab, *wqt, *wkt, *wvt, *wot;
    cudaGetSymbolAddress((void**)&qb,  g_q);
    cudaGetSymbolAddress((void**)&kb,  g_k);
    cudaGetSymbolAddress((void**)&vb,  g_v);
    cudaGetSymbolAddress((void**)&ob,  g_o);
    cudaGetSymbolAddress((void**)&ab,  g_a);
    cudaGetSymbolAddress((void**)&wqt, g_wqt);
    cudaGetSymbolAddress((void**)&wkt, g_wkt);
    cudaGetSymbolAddress((void**)&wvt, g_wvt);
    cudaGetSymbolAddress((void**)&wot, g_wot);

    cudaFuncSetAttribute(tc_gemm_kernel, cudaFuncAttributeMaxDynamicSharedMemorySize,
                         GEMM_SMEM);
    cudaFuncSetAttribute(tc_gemm256_kernel, cudaFuncAttributeMaxDynamicSharedMemorySize,
                         GEMM256_SMEM);
    cudaFuncSetAttribute(flash_tc_kernel, cudaFuncAttributeMaxDynamicSharedMemorySize,
                         FLASH_SMEM_BYTES);

    // Round+permute A (hidden); transpose+round+permute weights into [N][K]
    perm_round_kernel<<<(ROWS * HID / 8 + 255) / 256, 256>>>(hidden, ab, ROWS * HID / 8);
    transpose_round_kernel<<<dim3(QCOLS / 32, HID / 32), dim3(32, 8)>>>(wq, wqt, HID, QCOLS);
    transpose_round_kernel<<<dim3(KVCOLS / 32, HID / 32), dim3(32, 8)>>>(wk, wkt, HID, KVCOLS);
    transpose_round_kernel<<<dim3(KVCOLS / 32, HID / 32), dim3(32, 8)>>>(wv, wvt, HID, KVCOLS);
    transpose_round_kernel<<<dim3(HID / 32, QCOLS / 32), dim3(32, 8)>>>(wo, wot, QCOLS, HID);

    // Projections: big-tile for Q, 128x128 for K/V (V rounded for cp.async)
    tc_gemm256_kernel<<<dim3(QCOLS / 256, ROWS / 128), 256, GEMM256_SMEM>>>(ab, wqt, qb, ROWS, QCOLS, HID);
    tc_gemm_kernel<<<dim3(KVCOLS / 128, ROWS / 128), 256, GEMM_SMEM>>>(ab, wkt, kb, ROWS, KVCOLS, HID, 0);
    tc_gemm_kernel<<<dim3(KVCOLS / 128, ROWS / 128), 256, GEMM_SMEM>>>(ab, wvt, vb, ROWS, KVCOLS, HID, 1);

    // RMSNorm + RoPE (stores tf32-rounded, k-permuted)
    rmsrope_kernel<<<(ROWS * HQ) / 8, 256>>>(qb, qnw, cosb, sinb, HQ);
    rmsrope_kernel<<<(ROWS * HKV) / 8, 256>>>(kb, knw, cosb, sinb, HKV);

    // Flash attention (tf32 TCs; output already permuted+rounded)
    flash_tc_kernel<<<dim3(SS / 128, HQ, BB), 256, FLASH_SMEM_BYTES>>>(qb, kb, vb, ob);

    // Output projection (big tile)
    tc_gemm256_kernel<<<dim3(HID / 256, ROWS / 128), 256, GEMM256_SMEM>>>(ob, wot, out, ROWS, HID, QCOLS);
}

// round 13
// speedup vs baseline: 6.7285x; 1.9521x over previous
#include <cuda_runtime.h>
#include <cuda_fp16.h>
#include <cstdint>
#include <math.h>

// Problem constants
#define BB 2
#define SS 2048
#define HID 2048
#define HQ 32
#define HKV 4
#define DH 128
#define ROWS (BB*SS)          // 4096
#define QCOLS (HQ*DH)         // 4096
#define KVCOLS (HKV*DH)       // 512
#define SCALE 0.08838834764831845f
#define EPS 1e-6f

// Scratch (device globals; zero-init BSS, no allocation)
__device__ __half g_q[(size_t)ROWS * QCOLS];     // natural fp16
__device__ __half g_k[(size_t)ROWS * KVCOLS];
__device__ __half g_v[(size_t)ROWS * KVCOLS];
__device__ __half g_o[(size_t)ROWS * QCOLS];     // permuted fp16 (O-proj A)
__device__ __half g_a[(size_t)ROWS * HID];       // permuted fp16 hidden
__device__ __half g_wqt[(size_t)QCOLS * HID];    // [N][K] permuted fp16
__device__ __half g_wkt[(size_t)KVCOLS * HID];
__device__ __half g_wvt[(size_t)KVCOLS * HID];
__device__ __half g_wot[(size_t)HID * QCOLS];

// ---------------------------------------------------------------------------
// Helpers
// ---------------------------------------------------------------------------
__device__ __forceinline__ uint32_t smem_u32(const void* p) {
    uint32_t a;
    asm("{ .reg .u64 t; cvta.to.shared.u64 t, %1; cvt.u32.u64 %0, t; }"
        : "=r"(a) : "l"(p));
    return a;
}

#define CPA16(s, g) \
    asm volatile("cp.async.cg.shared.global [%0], [%1], 16;" :: "r"(s), "l"(g))
#define CPA_COMMIT() asm volatile("cp.async.commit_group;")
#define CPA_WAIT(n)  asm volatile("cp.async.wait_group %0;" :: "n"(n))

// m16n8k16 fp16 MMA (sm_80+ baseline PTX), fp32 accumulate
__device__ __forceinline__ void mma_f16(float c[4],
                                        uint32_t a0, uint32_t a1,
                                        uint32_t a2, uint32_t a3,
                                        uint32_t b0, uint32_t b1) {
    asm volatile(
        "mma.sync.aligned.m16n8k16.row.col.f32.f16.f16.f32 "
        "{%0,%1,%2,%3}, {%4,%5,%6,%7}, {%8,%9}, {%0,%1,%2,%3};"
        : "+f"(c[0]), "+f"(c[1]), "+f"(c[2]), "+f"(c[3])
        : "r"(a0), "r"(a1), "r"(a2), "r"(a3), "r"(b0), "r"(b1));
}

#define LDSM4(r0, r1, r2, r3, addr) \
    asm volatile("ldmatrix.sync.aligned.m8n8.x4.shared.b16 {%0,%1,%2,%3}, [%4];" \
        : "=r"(r0), "=r"(r1), "=r"(r2), "=r"(r3) : "r"(addr))
#define LDSM4T(r0, r1, r2, r3, addr) \
    asm volatile("ldmatrix.sync.aligned.m8n8.x4.trans.shared.b16 {%0,%1,%2,%3}, [%4];" \
        : "=r"(r0), "=r"(r1), "=r"(r2), "=r"(r3) : "r"(addr))

__device__ __forceinline__ uint32_t pack_h2(float lo, float hi) {
    __half2 h = __floats2half2_rn(lo, hi);
    return *(uint32_t*)&h;
}

// ---------------------------------------------------------------------------
// f32 -> permuted fp16 copy. Per 16-element k-group, logical half-pairs
// p(=elems 2p,2p+1) stored at position p<4 ? 2p : 2(p-4)+1, so fp16 MMA
// fragment elements (k-lo, k-hi) are adjacent 4B -> LDS.64 pairs in GEMM.
// n16 = n/16.
// ---------------------------------------------------------------------------
__global__ void perm_half_kernel(const float* __restrict__ in,
                                 __half* __restrict__ out, int n16)
{
    int i = blockIdx.x * blockDim.x + threadIdx.x;
    if (i >= n16) return;
    const float4* p = (const float4*)(in + (size_t)16 * i);
    float4 f0 = p[0], f1 = p[1], f2 = p[2], f3 = p[3];
    __half2 h[8];
    h[0] = __floats2half2_rn(f0.x, f0.y);   // pair 0
    h[1] = __floats2half2_rn(f2.x, f2.y);   // pair 4
    h[2] = __floats2half2_rn(f0.z, f0.w);   // pair 1
    h[3] = __floats2half2_rn(f2.z, f2.w);   // pair 5
    h[4] = __floats2half2_rn(f1.x, f1.y);   // pair 2
    h[5] = __floats2half2_rn(f3.x, f3.y);   // pair 6
    h[6] = __floats2half2_rn(f1.z, f1.w);   // pair 3
    h[7] = __floats2half2_rn(f3.z, f3.w);   // pair 7
    uint4* q = (uint4*)(out + (size_t)16 * i);
    q[0] = *(uint4*)h;
    q[1] = *(uint4*)(h + 4);
}

// ---------------------------------------------------------------------------
// Transpose + fp16 + k-permute: in [K][N] f32 -> out [N][K] permuted fp16.
// ---------------------------------------------------------------------------
__global__ void transpose_half_kernel(const float* __restrict__ in,
                                      __half* __restrict__ out, int K, int N)
{
    __shared__ float tile[32][33];
    const int bx = blockIdx.x * 32;   // N offset
    const int by = blockIdx.y * 32;   // K offset
    const int tx = threadIdx.x, ty = threadIdx.y;
#pragma unroll
    for (int i = 0; i < 32; i += 8)
        tile[ty + i][tx] = in[(size_t)(by + ty + i) * N + bx + tx];
    __syncthreads();
    const int w   = tx & 15;
    const int pr  = w >> 1;
    const int odd = w & 1;
    const int sp  = (pr < 4) ? 2 * pr : 2 * pr - 7;
    const int kk  = (tx & ~15) + 2 * sp + odd;
#pragma unroll
    for (int i = 0; i < 32; i += 8)
        out[(size_t)(bx + ty + i) * K + by + kk] = __float2half_rn(tile[tx][ty + i]);
}

// ---------------------------------------------------------------------------
// fp16 GEMM cores. C[M,N] = A[M,K] @ Bt[N,K]^T; A,Bt permuted fp16.
// BK=64 halves (128B data rows, padded to 160B = 40 4B-pairs -> RS=40,
// uint2 fragment loads at stride 20, conflict-free). 3-stage cp.async.
// half_out: store fp16 natural; else f32.
// ---------------------------------------------------------------------------
#define RS 40
#define NSTAGE 3
#define ROWB 160                                   // bytes per smem row

__device__ __forceinline__ void load_rows(const __half* __restrict__ src,
                                          int K, int r0, int k0,
                                          char* dst, int id, int nrows)
{
    // id enumerates (row, seg): 8 segs of 16B per row
    int row = id >> 3, seg = id & 7;
    if (row < nrows)
        CPA16(smem_u32(dst + row * ROWB + seg * 16),
              src + (size_t)(r0 + row) * K + k0 + seg * 8);
}

// ---- 128x256 tile (big GEMMs) ----
#define STG256_BYTES ((128 + 256) * ROWB)          // 61440
#define GEMM256_SMEM (NSTAGE * STG256_BYTES)       // 184320

__global__ __launch_bounds__(256) void tc_gemm256h_kernel(
    const __half* __restrict__ A, const __half* __restrict__ Bt,
    void* __restrict__ C, int M, int N, int K, int half_out)
{
    extern __shared__ char smc[];
    const int t    = threadIdx.x;
    const int lane = t & 31, wid = t >> 5;
    const int wm   = wid >> 2, wn = wid & 3;
    const int bm   = blockIdx.y * 128, bn = blockIdx.x * 256;
    const int qr   = lane >> 2, qc = lane & 3;

    char* stg[NSTAGE];
#pragma unroll
    for (int s = 0; s < NSTAGE; s++) stg[s] = smc + s * STG256_BYTES;

    float c[4][8][4];
#pragma unroll
    for (int mt = 0; mt < 4; mt++)
#pragma unroll
        for (int nt = 0; nt < 8; nt++)
#pragma unroll
            for (int r = 0; r < 4; r++) c[mt][nt][r] = 0.f;

    const int NIT = K >> 6;
#pragma unroll
    for (int s = 0; s < 2; s++) {
#pragma unroll
        for (int u = 0; u < 4; u++)
            load_rows(A, K, bm, s * 64, stg[s], t + u * 256, 128);
#pragma unroll
        for (int u = 0; u < 8; u++)
            load_rows(Bt, K, bn, s * 64, stg[s] + 128 * ROWB, t + u * 256, 256);
        CPA_COMMIT();
    }

    for (int it = 0; it < NIT; it++) {
        CPA_WAIT(1);
        __syncthreads();
        if (it + 2 < NIT) {
            char* st = stg[(it + 2) % NSTAGE];
#pragma unroll
            for (int u = 0; u < 4; u++)
                load_rows(A, K, bm, (it + 2) * 64, st, t + u * 256, 128);
#pragma unroll
            for (int u = 0; u < 8; u++)
                load_rows(Bt, K, bn, (it + 2) * 64, st + 128 * ROWB, t + u * 256, 256);
        }
        CPA_COMMIT();

        const uint2* As2 = (const uint2*)stg[it % NSTAGE];
        const uint2* Bs2 = As2 + 128 * (ROWB / 8);

#pragma unroll
        for (int ks = 0; ks < 4; ks++) {
            uint32_t a[4][4], b[8][2];
            const int kp = 4 * ks + qc;
#pragma unroll
            for (int mt = 0; mt < 4; mt++) {
                const int r = wm * 64 + mt * 16 + qr;
                uint2 p0 = As2[r * 20 + kp];
                uint2 p1 = As2[(r + 8) * 20 + kp];
                a[mt][0] = p0.x; a[mt][2] = p0.y;
                a[mt][1] = p1.x; a[mt][3] = p1.y;
            }
#pragma unroll
            for (int nt = 0; nt < 8; nt++) {
                const int n = wn * 64 + nt * 8 + qr;
                uint2 pb = Bs2[n * 20 + kp];
                b[nt][0] = pb.x; b[nt][1] = pb.y;
            }
#pragma unroll
            for (int mt = 0; mt < 4; mt++)
#pragma unroll
                for (int nt = 0; nt < 8; nt++)
                    mma_f16(c[mt][nt], a[mt][0], a[mt][1], a[mt][2], a[mt][3],
                            b[nt][0], b[nt][1]);
        }
    }

#pragma unroll
    for (int mt = 0; mt < 4; mt++) {
        const int row = bm + wm * 64 + mt * 16 + qr;
#pragma unroll
        for (int nt = 0; nt < 8; nt++) {
            const int col = bn + wn * 64 + nt * 8 + 2 * qc;
            if (half_out) {
                __half* Ch = (__half*)C;
                *(__half2*)&Ch[(size_t)row * N + col] =
                    __floats2half2_rn(c[mt][nt][0], c[mt][nt][1]);
                *(__half2*)&Ch[(size_t)(row + 8) * N + col] =
                    __floats2half2_rn(c[mt][nt][2], c[mt][nt][3]);
            } else {
                float* Cf = (float*)C;
                *(float2*)&Cf[(size_t)row * N + col] =
                    make_float2(c[mt][nt][0], c[mt][nt][1]);
                *(float2*)&Cf[(size_t)(row + 8) * N + col] =
                    make_float2(c[mt][nt][2], c[mt][nt][3]);
            }
        }
    }
}

// ---- 128x128 tile (KV projections) ----
#define STG128_BYTES (256 * ROWB)                  // 40960
#define GEMM128_SMEM (NSTAGE * STG128_BYTES)       // 122880

__global__ __launch_bounds__(256) void tc_gemm128h_kernel(
    const __half* __restrict__ A, const __half* __restrict__ Bt,
    __half* __restrict__ C, int M, int N, int K)
{
    extern __shared__ char smc[];
    const int t    = threadIdx.x;
    const int lane = t & 31, wid = t >> 5;
    const int wm   = wid >> 2, wn = wid & 3;
    const int bm   = blockIdx.y * 128, bn = blockIdx.x * 128;
    const int qr   = lane >> 2, qc = lane & 3;

    char* stg[NSTAGE];
#pragma unroll
    for (int s = 0; s < NSTAGE; s++) stg[s] = smc + s * STG128_BYTES;

    float c[4][4][4];
#pragma unroll
    for (int mt = 0; mt < 4; mt++)
#pragma unroll
        for (int nt = 0; nt < 4; nt++)
#pragma unroll
            for (int r = 0; r < 4; r++) c[mt][nt][r] = 0.f;

    const int NIT = K >> 6;
#pragma unroll
    for (int s = 0; s < 2; s++) {
#pragma unroll
        for (int u = 0; u < 4; u++)
            load_rows(A, K, bm, s * 64, stg[s], t + u * 256, 128);
#pragma unroll
        for (int u = 0; u < 4; u++)
            load_rows(Bt, K, bn, s * 64, stg[s] + 128 * ROWB, t + u * 256, 128);
        CPA_COMMIT();
    }

    for (int it = 0; it < NIT; it++) {
        CPA_WAIT(1);
        __syncthreads();
        if (it + 2 < NIT) {
            char* st = stg[(it + 2) % NSTAGE];
#pragma unroll
            for (int u = 0; u < 4; u++)
                load_rows(A, K, bm, (it + 2) * 64, st, t + u * 256, 128);
#pragma unroll
            for (int u = 0; u < 4; u++)
                load_rows(Bt, K, bn, (it + 2) * 64, st + 128 * ROWB, t + u * 256, 128);
        }
        CPA_COMMIT();

        const uint2* As2 = (const uint2*)stg[it % NSTAGE];
        const uint2* Bs2 = As2 + 128 * (ROWB / 8);

#pragma unroll
        for (int ks = 0; ks < 4; ks++) {
            uint32_t a[4][4], b[4][2];
            const int kp = 4 * ks + qc;
#pragma unroll
            for (int mt = 0; mt < 4; mt++) {
                const int r = wm * 64 + mt * 16 + qr;
                uint2 p0 = As2[r * 20 + kp];
                uint2 p1 = As2[(r + 8) * 20 + kp];
                a[mt][0] = p0.x; a[mt][2] = p0.y;
                a[mt][1] = p1.x; a[mt][3] = p1.y;
            }
#pragma unroll
            for (int nt = 0; nt < 4; nt++) {
                const int n = wn * 32 + nt * 8 + qr;
                uint2 pb = Bs2[n * 20 + kp];
                b[nt][0] = pb.x; b[nt][1] = pb.y;
            }
#pragma unroll
            for (int mt = 0; mt < 4; mt++)
#pragma unroll
                for (int nt = 0; nt < 4; nt++)
                    mma_f16(c[mt][nt], a[mt][0], a[mt][1], a[mt][2], a[mt][3],
                            b[nt][0], b[nt][1]);
        }
    }

#pragma unroll
    for (int mt = 0; mt < 4; mt++) {
        const int row = bm + wm * 64 + mt * 16 + qr;
#pragma unroll
        for (int nt = 0; nt < 4; nt++) {
            const int col = bn + wn * 32 + nt * 8 + 2 * qc;
            *(__half2*)&C[(size_t)row * N + col] =
                __floats2half2_rn(c[mt][nt][0], c[mt][nt][1]);
            *(__half2*)&C[(size_t)(row + 8) * N + col] =
                __floats2half2_rn(c[mt][nt][2], c[mt][nt][3]);
        }
    }
}

// ---------------------------------------------------------------------------
// RMSNorm + RoPE on fp16, in place, natural layout. One warp per (row,head).
// Lane l owns d = 2l,2l+1 (half2) and d+64 pair -> RoPE stays in-lane.
// ---------------------------------------------------------------------------
__global__ void rmsrope_half_kernel(__half* __restrict__ x,
                                    const float* __restrict__ w,
                                    const float* __restrict__ cosb,
                                    const float* __restrict__ sinb, int nh)
{
    const int gwid = (blockIdx.x * blockDim.x + threadIdx.x) >> 5;
    const int lane = threadIdx.x & 31;
    const int total = ROWS * nh;
    if (gwid >= total) return;
    const int row = gwid / nh;
    const int h   = gwid - row * nh;
    const int s   = row & (SS - 1);

    __half* xp = x + (size_t)row * (nh * DH) + h * DH;
    __half2 lo = *(__half2*)(xp + 2 * lane);
    __half2 hi = *(__half2*)(xp + 64 + 2 * lane);
    float v0 = __low2float(lo), v1 = __high2float(lo);
    float v2 = __low2float(hi), v3 = __high2float(hi);

    float ssum = v0 * v0 + v1 * v1 + v2 * v2 + v3 * v3;
#pragma unroll
    for (int off = 16; off > 0; off >>= 1)
        ssum += __shfl_xor_sync(0xffffffffu, ssum, off);
    const float r = rsqrtf(ssum * (1.f / DH) + EPS);

    const float n0 = v0 * r * w[2 * lane];
    const float n1 = v1 * r * w[2 * lane + 1];
    const float n2 = v2 * r * w[64 + 2 * lane];
    const float n3 = v3 * r * w[64 + 2 * lane + 1];

    const float* cp = cosb + (size_t)s * DH;
    const float* sp = sinb + (size_t)s * DH;
    const float c0 = cp[2 * lane], c1 = cp[2 * lane + 1];
    const float c2 = cp[64 + 2 * lane], c3 = cp[64 + 2 * lane + 1];
    const float s0 = sp[2 * lane], s1 = sp[2 * lane + 1];
    const float s2 = sp[64 + 2 * lane], s3 = sp[64 + 2 * lane + 1];

    *(__half2*)(xp + 2 * lane)      = __floats2half2_rn(n0 * c0 - n2 * s0,
                                                        n1 * c1 - n3 * s1);
    *(__half2*)(xp + 64 + 2 * lane) = __floats2half2_rn(n2 * c2 + n0 * s2,
                                                        n3 * c3 + n1 * s3);
}

// ---------------------------------------------------------------------------
// Causal GQA flash attention, fp16 m16n8k16 + ldmatrix + cp.async pipeline.
// BM=128, BN=64. 8 warps; warp owns 16 q-rows (row stats in-warp).
// Q/K/V natural fp16, FDH=136-half rows (272B: ldmatrix conflict-free).
// P never touches smem: fp16 A-frags packed from score registers.
// K and V double-buffered; one cp.async group per iteration.
// Epilogue stores permuted fp16 (direct O-proj input).
// ---------------------------------------------------------------------------
#define FDH 136
#define FLASH_SMEM ((128 + 4 * 64) * FDH * 2)     // 104448 bytes

__device__ __forceinline__ void flash_ld_kv(const __half* __restrict__ src,
                                            __half* __restrict__ dst, int t)
{
#pragma unroll
    for (int u = 0; u < 4; u++) {
        int id = t + u * 256;
        int row = id >> 4, seg = id & 15;
        CPA16(smem_u32(dst + row * FDH + seg * 8),
              src + (size_t)row * KVCOLS + seg * 8);
    }
}

__global__ __launch_bounds__(256) void flash_h_kernel(
    const __half* __restrict__ Q, const __half* __restrict__ K,
    const __half* __restrict__ V, __half* __restrict__ O)
{
    extern __shared__ __half smh[];
    __half* Qs  = smh;
    __half* Ksb[2] = { smh + 128 * FDH, smh + 192 * FDH };
    __half* Vsb[2] = { smh + 256 * FDH, smh + 320 * FDH };

    const int qt = blockIdx.x;
    const int h  = blockIdx.y;
    const int b  = blockIdx.z;
    const int t  = threadIdx.x;
    const int wid  = t >> 5;
    const int lane = t & 31;
    const int qr = lane >> 2, qc = lane & 3;
    const int hk = h >> 3;

    const size_t qbase  = ((size_t)(b * SS) + qt * 128) * QCOLS + h * DH;
    const size_t kvrow0 = (size_t)(b * SS) * KVCOLS + hk * DH;
    const int nkt = (qt + 1) * 2;

    // ldmatrix lane bases
    const uint32_t qa = smem_u32(Qs) +
        2 * ((16 * wid + ((lane >> 3) & 1) * 8 + (lane & 7)) * FDH + (lane >> 4) * 8);
    const uint32_t kb_rel = 2 * (((lane >> 4) * 8 + (lane & 7)) * FDH
                                 + ((lane >> 3) & 1) * 8);
    const uint32_t vb_rel = 2 * ((((lane >> 3) & 1) * 8 + (lane & 7)) * FDH
                                 + (lane >> 4) * 8);
    const uint32_t kbb[2] = { smem_u32(Ksb[0]) + kb_rel, smem_u32(Ksb[1]) + kb_rel };
    const uint32_t vbb[2] = { smem_u32(Vsb[0]) + vb_rel, smem_u32(Vsb[1]) + vb_rel };

    // Prologue: G0 = Q + K0 + V0; G1 = K1 + V1
#pragma unroll
    for (int u = 0; u < 8; u++) {
        int id = t + u * 256;
        int row = id >> 4, seg = id & 15;
        CPA16(smem_u32(Qs + row * FDH + seg * 8),
              Q + qbase + (size_t)row * QCOLS + seg * 8);
    }
    flash_ld_kv(K + kvrow0, Ksb[0], t);
    flash_ld_kv(V + kvrow0, Vsb[0], t);
    CPA_COMMIT();
    flash_ld_kv(K + kvrow0 + (size_t)64 * KVCOLS, Ksb[1], t);
    flash_ld_kv(V + kvrow0 + (size_t)64 * KVCOLS, Vsb[1], t);
    CPA_COMMIT();

    float oa[16][4];
#pragma unroll
    for (int nt = 0; nt < 16; nt++)
#pragma unroll
        for (int r = 0; r < 4; r++) oa[nt][r] = 0.f;
    float m0 = -1e30f, m1 = -1e30f, l0 = 0.f, l1 = 0.f;

    const int row0 = qt * 128 + 16 * wid + qr;
    const int row1 = row0 + 8;

    for (int kt = 0; kt < nkt; kt++) {
        CPA_WAIT(1);
        __syncthreads();

        const uint32_t kb = kbb[kt & 1];
        const uint32_t vb = vbb[kt & 1];

        // ---- S = Q @ K^T ----
        float s[8][4];
#pragma unroll
        for (int nt = 0; nt < 8; nt++)
#pragma unroll
            for (int r = 0; r < 4; r++) s[nt][r] = 0.f;

#pragma unroll
        for (int ks = 0; ks < 8; ks++) {
            uint32_t a0, a1, a2, a3;
            LDSM4(a0, a1, a2, a3, qa + 32 * ks);
#pragma unroll
            for (int ntp = 0; ntp < 4; ntp++) {
                uint32_t b00, b01, b10, b11;
                LDSM4(b00, b01, b10, b11,
                      kb + 2 * (16 * ntp * FDH + 16 * ks));
                mma_f16(s[2 * ntp],     a0, a1, a2, a3, b00, b01);
                mma_f16(s[2 * ntp + 1], a0, a1, a2, a3, b10, b11);
            }
        }

        // ---- scale + causal mask + row max ----
        float mx0 = -1e30f, mx1 = -1e30f;
        const int colb = kt * 64 + 2 * qc;
#pragma unroll
        for (int nt = 0; nt < 8; nt++) {
            const int c0 = colb + 8 * nt, c1 = c0 + 1;
            s[nt][0] = (c0 <= row0) ? s[nt][0] * SCALE : -1e30f;
            s[nt][1] = (c1 <= row0) ? s[nt][1] * SCALE : -1e30f;
            s[nt][2] = (c0 <= row1) ? s[nt][2] * SCALE : -1e30f;
            s[nt][3] = (c1 <= row1) ? s[nt][3] * SCALE : -1e30f;
            mx0 = fmaxf(mx0, fmaxf(s[nt][0], s[nt][1]));
            mx1 = fmaxf(mx1, fmaxf(s[nt][2], s[nt][3]));
        }
        mx0 = fmaxf(mx0, __shfl_xor_sync(0xffffffffu, mx0, 1));
        mx0 = fmaxf(mx0, __shfl_xor_sync(0xffffffffu, mx0, 2));
        mx1 = fmaxf(mx1, __shfl_xor_sync(0xffffffffu, mx1, 1));
        mx1 = fmaxf(mx1, __shfl_xor_sync(0xffffffffu, mx1, 2));

        const float mn0 = fmaxf(m0, mx0), mn1 = fmaxf(m1, mx1);
        const float sc0 = __expf(m0 - mn0), sc1 = __expf(m1 - mn1);
        m0 = mn0; m1 = mn1;

        // ---- exp -> register-resident fp16 P A-frags ----
        uint32_t pa[4][4];
        float rs0 = 0.f, rs1 = 0.f;
#pragma unroll
        for (int nt = 0; nt < 8; nt++) {
            float e0 = __expf(s[nt][0] - mn0);
            float e1 = __expf(s[nt][1] - mn0);
            float e2 = __expf(s[nt][2] - mn1);
            float e3 = __expf(s[nt][3] - mn1);
            rs0 += e0 + e1; rs1 += e2 + e3;
            pa[nt >> 1][(nt & 1) * 2]     = pack_h2(e0, e1);
            pa[nt >> 1][(nt & 1) * 2 + 1] = pack_h2(e2, e3);
        }
        rs0 += __shfl_xor_sync(0xffffffffu, rs0, 1);
        rs0 += __shfl_xor_sync(0xffffffffu, rs0, 2);
        rs1 += __shfl_xor_sync(0xffffffffu, rs1, 1);
        rs1 += __shfl_xor_sync(0xffffffffu, rs1, 2);
        l0 = l0 * sc0 + rs0;
        l1 = l1 * sc1 + rs1;

#pragma unroll
        for (int nt = 0; nt < 16; nt++) {
            oa[nt][0] *= sc0; oa[nt][1] *= sc0;
            oa[nt][2] *= sc1; oa[nt][3] *= sc1;
        }

        // ---- O += P @ V (V via ldmatrix.trans) ----
#pragma unroll
        for (int kvp = 0; kvp < 4; kvp++) {
            const uint32_t vbase = vb + 2 * (16 * kvp * FDH);
#pragma unroll
            for (int ntp = 0; ntp < 8; ntp++) {
                uint32_t b00, b01, b10, b11;
                LDSM4T(b00, b01, b10, b11, vbase + 2 * (16 * ntp));
                mma_f16(oa[2 * ntp], pa[kvp][0], pa[kvp][1], pa[kvp][2],
                        pa[kvp][3], b00, b01);
                mma_f16(oa[2 * ntp + 1], pa[kvp][0], pa[kvp][1], pa[kvp][2],
                        pa[kvp][3], b10, b11);
            }
        }

        __syncthreads();   // all warps done with buffer (kt&1) before refill
        if (kt + 2 < nkt) {
            flash_ld_kv(K + kvrow0 + (size_t)(kt + 2) * 64 * KVCOLS, Ksb[kt & 1], t);
            flash_ld_kv(V + kvrow0 + (size_t)(kt + 2) * 64 * KVCOLS, Vsb[kt & 1], t);
        }
        CPA_COMMIT();
    }

    // ---- epilogue: normalize, store permuted fp16 ----
    const float inv0 = 1.f / l0, inv1 = 1.f / l1;
    __half* o0 = O + qbase + (size_t)(16 * wid + qr) * QCOLS;
    __half* o1 = O + qbase + (size_t)(16 * wid + qr + 8) * QCOLS;
#pragma unroll
    for (int nt = 0; nt < 16; nt++) {
        const int p  = (nt & 1) * 4 + qc;
        const int sp = (p < 4) ? 2 * p : 2 * p - 7;
        const int idx = (nt >> 1) * 16 + 2 * sp;
        *(__half2*)(o0 + idx) = __floats2half2_rn(oa[nt][0] * inv0,
                                                  oa[nt][1] * inv0);
        *(__half2*)(o1 + idx) = __floats2half2_rn(oa[nt][2] * inv1,
                                                  oa[nt][3] * inv1);
    }
}

// ---------------------------------------------------------------------------
extern "C" void kernel_launch(void* const* d_in, const int* in_sizes, int n_in,
                              void* d_out, int out_size)
{
    const float* hidden = (const float*)d_in[0];
    const float* cosb   = (const float*)d_in[1];
    const float* sinb   = (const float*)d_in[2];
    const float* wq     = (const float*)d_in[3];
    const float* wk     = (const float*)d_in[4];
    const float* wv     = (const float*)d_in[5];
    const float* wo     = (const float*)d_in[6];
    const float* qnw    = (const float*)d_in[7];
    const float* knw    = (const float*)d_in[8];
    float* out = (float*)d_out;

    __half *qb, *kb, *vb, *ob, *ab, *wqt, *wkt, *wvt, *wot;
    cudaGetSymbolAddress((void**)&qb,  g_q);
    cudaGetSymbolAddress((void**)&kb,  g_k);
    cudaGetSymbolAddress((void**)&vb,  g_v);
    cudaGetSymbolAddress((void**)&ob,  g_o);
    cudaGetSymbolAddress((void**)&ab,  g_a);
    cudaGetSymbolAddress((void**)&wqt, g_wqt);
    cudaGetSymbolAddress((void**)&wkt, g_wkt);
    cudaGetSymbolAddress((void**)&wvt, g_wvt);
    cudaGetSymbolAddress((void**)&wot, g_wot);

    cudaFuncSetAttribute(tc_gemm256h_kernel,
                         cudaFuncAttributeMaxDynamicSharedMemorySize, GEMM256_SMEM);
    cudaFuncSetAttribute(tc_gemm128h_kernel,
                         cudaFuncAttributeMaxDynamicSharedMemorySize, GEMM128_SMEM);
    cudaFuncSetAttribute(flash_h_kernel,
                         cudaFuncAttributeMaxDynamicSharedMemorySize, FLASH_SMEM);

    // Prep: hidden -> permuted fp16; weights -> [N][K] permuted fp16
    perm_half_kernel<<<(ROWS * HID / 16 + 255) / 256, 256>>>(hidden, ab, ROWS * HID / 16);
    transpose_half_kernel<<<dim3(QCOLS / 32, HID / 32), dim3(32, 8)>>>(wq, wqt, HID, QCOLS);
    transpose_half_kernel<<<dim3(KVCOLS / 32, HID / 32), dim3(32, 8)>>>(wk, wkt, HID, KVCOLS);
    transpose_half_kernel<<<dim3(KVCOLS / 32, HID / 32), dim3(32, 8)>>>(wv, wvt, HID, KVCOLS);
    transpose_half_kernel<<<dim3(HID / 32, QCOLS / 32), dim3(32, 8)>>>(wo, wot, QCOLS, HID);

    // Projections (fp16 tensor cores), fp16 natural outputs
    tc_gemm256h_kernel<<<dim3(QCOLS / 256, ROWS / 128), 256, GEMM256_SMEM>>>(
        ab, wqt, qb, ROWS, QCOLS, HID, 1);
    tc_gemm128h_kernel<<<dim3(KVCOLS / 128, ROWS / 128), 256, GEMM128_SMEM>>>(
        ab, wkt, kb, ROWS, KVCOLS, HID);
    tc_gemm128h_kernel<<<dim3(KVCOLS / 128, ROWS / 128), 256, GEMM128_SMEM>>>(
        ab, wvt, vb, ROWS, KVCOLS, HID);

    // RMSNorm + RoPE (fp16 in place)
    rmsrope_half_kernel<<<(ROWS * HQ) / 8, 256>>>(qb, qnw, cosb, sinb, HQ);
    rmsrope_half_kernel<<<(ROWS * HKV) / 8, 256>>>(kb, knw, cosb, sinb, HKV);

    // Flash attention (fp16, ldmatrix, register P)
    flash_h_kernel<<<dim3(SS / 128, HQ, BB), 256, FLASH_SMEM>>>(qb, kb, vb, ob);

    // Output projection (f32 output)
    tc_gemm256h_kernel<<<dim3(HID / 256, ROWS / 128), 256, GEMM256_SMEM>>>(
        ob, wot, out, ROWS, HID, QCOLS, 0);
}